// round 6
// baseline (speedup 1.0000x reference)
#include <cuda_runtime.h>
#include <cuda_bf16.h>
#include <math.h>
#include <stdint.h>

#define M_LIB   200000
#define N_PATCH 676
#define NPAD    768
#define DIM     384
#define IMG     224
#define SIGMA   4.0f
#define KRAD    16

#define NTILES  43              // 128-row tiles per stripe; 37 stripes
#define STRIPE  (128*NTILES)    // 5504
#define STG_BYTES (128*256)     // one stage: 128 rows x 128 k-elems bf16 (256B pitch)
#define SM_P    0               // patch chunk 192 x 768B = 147456
#define SM_L    147456
#define SM_MIN  (SM_L + 2*STG_BYTES)   // 212992
#define SMEM_MAIN (SM_MIN + 192*8)     // 214528

// ---------------- device scratch ----------------
__device__ __align__(16) __nv_bfloat16 g_lib_bf16[(size_t)M_LIB * DIM];
__device__ float g_ln[M_LIB];
__device__ float g_patch_n[N_PATCH * DIM];
__device__ __align__(16) __nv_bfloat16 g_patch_bf16[NPAD * DIM];
__device__ float g_pn[N_PATCH];
__device__ unsigned long long g_minbuf[NPAD];
__device__ float g_minval[N_PATCH];
__device__ int   g_sidx;
__device__ int   g_mstar_idx;
__device__ float g_sstar;
__device__ float g_d2star[M_LIB];
__device__ unsigned long long g_btop[64 * 5];
__device__ int   g_nn[5];
__device__ float g_map_a[IMG * IMG];
__device__ float g_map_b[IMG * IMG];

// ---------------- helpers ----------------
__device__ __forceinline__ unsigned fordu(float f) {
    unsigned u = __float_as_uint(f);
    return (u & 0x80000000u) ? ~u : (u | 0x80000000u);
}
__device__ __forceinline__ float fordu_inv(unsigned e) {
    return __uint_as_float((e & 0x80000000u) ? (e ^ 0x80000000u) : ~e);
}
__device__ __forceinline__ unsigned long long packkey(float v, int idx) {
    return ((unsigned long long)fordu(v) << 32) | (unsigned)idx;
}
__device__ __forceinline__ unsigned long long ullmin2(unsigned long long a, unsigned long long b) {
    return a < b ? a : b;
}
#define INF_F (__int_as_float(0x7f800000))

__device__ __forceinline__ uint32_t smem_u32(const void* p) {
    return (uint32_t)__cvta_generic_to_shared(p);
}

#define LDSM4(r0,r1,r2,r3,addr) \
    asm volatile("ldmatrix.sync.aligned.m8n8.x4.shared.b16 {%0,%1,%2,%3}, [%4];" \
        : "=r"(r0), "=r"(r1), "=r"(r2), "=r"(r3) : "r"(addr))
#define MMA16816(D,a0,a1,a2,a3,b0,b1) \
    asm volatile("mma.sync.aligned.m16n8k16.row.col.f32.bf16.bf16.f32 " \
        "{%0,%1,%2,%3},{%4,%5,%6,%7},{%8,%9},{%0,%1,%2,%3};" \
        : "+f"((D)[0]), "+f"((D)[1]), "+f"((D)[2]), "+f"((D)[3]) \
        : "r"(a0), "r"(a1), "r"(a2), "r"(a3), "r"(b0), "r"(b1))

__device__ __forceinline__ void cp16(uint32_t dst, const void* src, uint32_t nbytes) {
    asm volatile("cp.async.cg.shared.global [%0], [%1], 16, %2;"
                 :: "r"(dst), "l"(src), "r"(nbytes) : "memory");
}
#define CP_COMMIT() asm volatile("cp.async.commit_group;" ::: "memory")
#define CP_WAIT1()  asm volatile("cp.async.wait_group 1;" ::: "memory")

// ---------------- 1. normalize patch ----------------
__global__ void k_prep_patch(const float* __restrict__ patch) {
    int n = blockIdx.x, t = threadIdx.x;  // 128 thr
    if (n >= N_PATCH) {
        #pragma unroll
        for (int j = 0; j < 3; j++) g_patch_bf16[n * DIM + t + 128 * j] = __float2bfloat16(0.f);
        return;
    }
    __shared__ float red[128];
    float v[3]; float ss = 0.f;
    #pragma unroll
    for (int j = 0; j < 3; j++) { v[j] = patch[(size_t)n * DIM + t + 128 * j]; ss += v[j] * v[j]; }
    red[t] = ss; __syncthreads();
    for (int s = 64; s > 0; s >>= 1) { if (t < s) red[t] += red[t + s]; __syncthreads(); }
    float denom = fmaxf(sqrtf(red[0]), 1e-12f);
    __syncthreads();
    float pn = 0.f;
    #pragma unroll
    for (int j = 0; j < 3; j++) {
        float x = v[j] / denom; pn += x * x;
        g_patch_n[n * DIM + t + 128 * j] = x;
        g_patch_bf16[n * DIM + t + 128 * j] = __float2bfloat16(x);
    }
    red[t] = pn; __syncthreads();
    for (int s = 64; s > 0; s >>= 1) { if (t < s) red[t] += red[t + s]; __syncthreads(); }
    if (t == 0) g_pn[n] = red[0];
}

// ---------------- 2. lib fp32 -> bf16 + ln ----------------
__global__ void k_prep_lib(const float* __restrict__ lib) {
    int w = threadIdx.x >> 5, lane = threadIdx.x & 31;
    int row = blockIdx.x * 8 + w;
    const float4* src = (const float4*)(lib + (size_t)row * DIM);
    __nv_bfloat162* dst = (__nv_bfloat162*)(g_lib_bf16 + (size_t)row * DIM);
    float ss = 0.f;
    #pragma unroll
    for (int j = 0; j < 3; j++) {
        float4 f = src[lane + 32 * j];
        ss += f.x * f.x + f.y * f.y + f.z * f.z + f.w * f.w;
        dst[2 * (lane + 32 * j)]     = __floats2bfloat162_rn(f.x, f.y);
        dst[2 * (lane + 32 * j) + 1] = __floats2bfloat162_rn(f.z, f.w);
    }
    for (int o = 16; o; o >>= 1) ss += __shfl_xor_sync(0xffffffffu, ss, o);
    if (lane == 0) g_ln[row] = ss;
}

__global__ void k_init() {
    for (int i = threadIdx.x; i < NPAD; i += blockDim.x) g_minbuf[i] = ~0ull;
}

// ---------------- 4. fused bf16 HMMA GEMM + per-patch-row max-dot ----------
// grid 148 = 4 n-chunks x 37 stripes; 384 threads = 12 warps as 2 wm x 6 wn.
// CTA tile 128m x 192n, warp tile 64m x 32n: 6 LDSM.x4 per 16 MMA (192 B/MMA).
// Lib streamed as 128-row tiles in 3 k-thirds (256B pitch), 2-stage cp.async.
__global__ void __launch_bounds__(384, 1) k_main() {
    extern __shared__ char sm[];
    const uint32_t smb = smem_u32(sm);
    unsigned long long* sMin = (unsigned long long*)(sm + SM_MIN);
    const int tid = threadIdx.x;
    const int warp = tid >> 5, lane = tid & 31;
    const int nc = blockIdx.x & 3;
    const int mBase = (blockIdx.x >> 2) * STRIPE;

    if (tid < 192) sMin[tid] = ~0ull;

    // --- stage resident patch chunk [192 x 384] bf16, swizzled 768B rows ---
    for (int i = tid; i < 192 * 48; i += 384) {
        int r = i / 48, u = i % 48;
        uint32_t dst = smb + SM_P + r * 768 + (((u ^ (r & 7))) << 4);
        cp16(dst, g_patch_bf16 + (size_t)(nc * 192 + r) * DIM + u * 8, 16);
    }
    CP_COMMIT();

    // --- prologue: stage0 = tile0 third0, stage1 = tile0 third1 ---
    #pragma unroll
    for (int p = 0; p < 2; p++) {
        for (int i = tid; i < 128 * 16; i += 384) {
            int r = i >> 4, u = i & 15;
            int g = mBase + r;
            uint32_t dst = smb + SM_L + p * STG_BYTES + r * 256 + (((u ^ (r & 7))) << 4);
            cp16(dst, g_lib_bf16 + (size_t)min(g, M_LIB - 1) * DIM + p * 128 + u * 8,
                 (g < M_LIB) ? 16u : 0u);
        }
        CP_COMMIT();
    }

    // --- per-thread invariants ---
    const int wm = warp & 1, wn = warp >> 1;      // 2 x 6, warp tile 64m x 32n
    const unsigned hiA = (lane >> 4);
    const unsigned hiB = (lane >> 3) & 1;
    unsigned baseA[4], swA[4];
    #pragma unroll
    for (int mf = 0; mf < 4; mf++) {
        unsigned rA = 64 * wm + 16 * mf + (lane & 15);
        baseA[mf] = rA * 256;
        swA[mf] = rA & 7;
    }
    unsigned pBase[2], swB[2];
    #pragma unroll
    for (int f2 = 0; f2 < 2; f2++) {
        unsigned rB = 32 * wn + 16 * f2 + (lane & 7) + ((lane >> 4) << 3);
        pBase[f2] = smb + SM_P + rB * 768;
        swB[f2] = rB & 7;
    }
    const int g8 = lane >> 2, tig = lane & 3;

    float runV[8]; int runI[8];
    #pragma unroll
    for (int j = 0; j < 8; j++) { runV[j] = -INF_F; runI[j] = 0; }

    float acc[16][4];
    #pragma unroll
    for (int g = 0; g < 16; g++) acc[g][0] = acc[g][1] = acc[g][2] = acc[g][3] = 0.f;

    int s = 0;
    for (int tile = 0; tile < NTILES; tile++) {
        #pragma unroll 1
        for (int q = 0; q < 3; q++) {
            CP_WAIT1();
            __syncthreads();
            // compute this stage: 8 ksteps, 4 A-frags + 2 B-frags, 16 MMAs
            const unsigned stgA = smb + SM_L + s * STG_BYTES;
            const unsigned kq = 16 * q + hiB;
            #pragma unroll
            for (int ks = 0; ks < 8; ks++) {
                unsigned a[4][4];
                unsigned uA = 2 * ks + hiA;
                #pragma unroll
                for (int mf = 0; mf < 4; mf++)
                    LDSM4(a[mf][0], a[mf][1], a[mf][2], a[mf][3],
                          stgA + baseA[mf] + (((uA ^ swA[mf])) << 4));
                unsigned uB = kq + 2 * ks;
                #pragma unroll
                for (int f2 = 0; f2 < 2; f2++) {
                    unsigned r0, r1, r2, r3;
                    LDSM4(r0, r1, r2, r3, pBase[f2] + (((uB ^ swB[f2])) << 4));
                    #pragma unroll
                    for (int mf = 0; mf < 4; mf++) {
                        MMA16816(acc[mf * 4 + 2 * f2],     a[mf][0], a[mf][1], a[mf][2], a[mf][3], r0, r1);
                        MMA16816(acc[mf * 4 + 2 * f2 + 1], a[mf][0], a[mf][1], a[mf][2], a[mf][3], r2, r3);
                    }
                }
            }
            __syncthreads();
            // prefetch (tile,q)+2 into this (now free) buffer
            {
                int qN = q + 2, tileN = tile;
                if (qN >= 3) { qN -= 3; tileN++; }
                if (tileN < NTILES) {
                    int mN = mBase + tileN * 128;
                    for (int i = tid; i < 128 * 16; i += 384) {
                        int r = i >> 4, u = i & 15;
                        int g = mN + r;
                        uint32_t dst = smb + SM_L + s * STG_BYTES + r * 256 + (((u ^ (r & 7))) << 4);
                        cp16(dst, g_lib_bf16 + (size_t)min(g, M_LIB - 1) * DIM + qN * 128 + u * 8,
                             (g < M_LIB) ? 16u : 0u);
                    }
                }
                CP_COMMIT();
            }
            s ^= 1;
        }
        // tile epilogue: fold 128-row tile into per-column running max dot
        int mt = mBase + tile * 128;
        #pragma unroll
        for (int g = 0; g < 16; g++) {
            int mf = g >> 2;
            int mlo = mt + 64 * wm + 16 * mf + g8, mhi = mlo + 8;
            bool okLo = mlo < M_LIB, okHi = mhi < M_LIB;
            #pragma unroll
            for (int c = 0; c < 2; c++) {
                int jj = ((g & 3) << 1) | c;
                float vlo = acc[g][c], vhi = acc[g][2 + c];
                if (okLo && vlo > runV[jj]) { runV[jj] = vlo; runI[jj] = mlo; }
                if (okHi && vhi > runV[jj]) { runV[jj] = vhi; runI[jj] = mhi; }
            }
            acc[g][0] = acc[g][1] = acc[g][2] = acc[g][3] = 0.f;
        }
    }

    // reduce over the 8 lanes sharing each column
    #pragma unroll
    for (int off = 4; off < 32; off <<= 1) {
        #pragma unroll
        for (int j = 0; j < 8; j++) {
            float ov = __shfl_xor_sync(0xffffffffu, runV[j], off);
            int   oi = __shfl_xor_sync(0xffffffffu, runI[j], off);
            if (ov > runV[j]) { runV[j] = ov; runI[j] = oi; }
        }
    }
    if (g8 == 0) {
        #pragma unroll
        for (int jj = 0; jj < 8; jj++) {
            int f2 = jj >> 2, nh = (jj >> 1) & 1, c = jj & 1;
            int col = 32 * wn + 16 * f2 + 8 * nh + 2 * tig + c;
            atomicMin(&sMin[col], packkey(-runV[jj], runI[jj]));
        }
    }
    __syncthreads();
    if (tid < 192) atomicMin(&g_minbuf[nc * 192 + tid], sMin[tid]);
}

// ---------------- 5. min_val per n + argmax over n ----------------
__global__ void k_nmin() {
    int t = threadIdx.x;  // 1024
    __shared__ float rv[1024]; __shared__ int ri[1024];
    float mv = -INF_F; int idx = 0;
    if (t < N_PATCH) {
        unsigned long long key = g_minbuf[t];
        int mi = (int)(key & 0xffffffffu);
        float v = fordu_inv((unsigned)(key >> 32));   // = -max_dot
        float d2 = g_pn[t] + g_ln[mi] + 2.f * v;
        mv = sqrtf(fmaxf(d2, 0.f));
        g_minval[t] = mv; idx = t;
    }
    rv[t] = mv; ri[t] = idx; __syncthreads();
    for (int s = 512; s > 0; s >>= 1) {
        if (t < s && rv[t + s] > rv[t]) { rv[t] = rv[t + s]; ri[t] = ri[t + s]; }
        __syncthreads();
    }
    if (t == 0) {
        g_sidx = ri[0]; g_sstar = rv[0];
        g_mstar_idx = (int)(g_minbuf[ri[0]] & 0xffffffffu);
    }
}

// ---------------- 6. d*^2 (shifted) over all lib rows ----------------
__global__ void k_pass2() {
    int w = threadIdx.x >> 5, lane = threadIdx.x & 31;
    int row = blockIdx.x * 8 + w;
    int msi = g_mstar_idx;
    const unsigned* a = (const unsigned*)(g_lib_bf16 + (size_t)row * DIM);
    const unsigned* b = (const unsigned*)(g_lib_bf16 + (size_t)msi * DIM);
    float dot = 0.f;
    #pragma unroll
    for (int j = 0; j < 6; j++) {
        unsigned ua = a[lane + 32 * j], ub = b[lane + 32 * j];
        float2 fa = __bfloat1622float2(*(__nv_bfloat162*)&ua);
        float2 fb = __bfloat1622float2(*(__nv_bfloat162*)&ub);
        dot = fmaf(fa.x, fb.x, dot); dot = fmaf(fa.y, fb.y, dot);
    }
    for (int o = 16; o; o >>= 1) dot += __shfl_xor_sync(0xffffffffu, dot, o);
    if (lane == 0) g_d2star[row] = g_ln[row] - 2.f * dot;
}

// ---------------- 7. top-5 smallest, block stage ----------------
__global__ void k_topscan() {
    unsigned long long best[5];
    #pragma unroll
    for (int r = 0; r < 5; r++) best[r] = ~0ull;
    for (int m = blockIdx.x * 256 + threadIdx.x; m < M_LIB; m += 64 * 256) {
        unsigned long long key = packkey(g_d2star[m], m);
        if (key < best[4]) {
            best[4] = key;
            #pragma unroll
            for (int r = 4; r > 0; r--)
                if (best[r] < best[r - 1]) { unsigned long long tm = best[r]; best[r] = best[r - 1]; best[r - 1] = tm; }
        }
    }
    __shared__ unsigned long long sb[5 * 256], red[256], winner;
    int t = threadIdx.x;
    #pragma unroll
    for (int r = 0; r < 5; r++) sb[r * 256 + t] = best[r];
    __syncthreads();
    for (int round = 0; round < 5; round++) {
        unsigned long long mn = ~0ull;
        #pragma unroll
        for (int r = 0; r < 5; r++) mn = ullmin2(mn, sb[r * 256 + t]);
        red[t] = mn; __syncthreads();
        for (int s = 128; s > 0; s >>= 1) { if (t < s) red[t] = ullmin2(red[t], red[t + s]); __syncthreads(); }
        if (t == 0) { winner = red[0]; g_btop[blockIdx.x * 5 + round] = red[0]; }
        __syncthreads();
        unsigned long long wv = winner;
        #pragma unroll
        for (int r = 0; r < 5; r++) if (sb[r * 256 + t] == wv) sb[r * 256 + t] = ~0ull;
        __syncthreads();
    }
}

// ---------------- 8. top-5 final merge ----------------
__global__ void k_topfinal() {
    __shared__ unsigned long long sb[320], red[256], winner;
    int t = threadIdx.x;  // 256
    sb[t] = g_btop[t];
    if (t < 64) sb[256 + t] = g_btop[256 + t];
    __syncthreads();
    for (int round = 0; round < 5; round++) {
        unsigned long long mn = sb[t];
        if (t < 64) mn = ullmin2(mn, sb[256 + t]);
        red[t] = mn; __syncthreads();
        for (int s = 128; s > 0; s >>= 1) { if (t < s) red[t] = ullmin2(red[t], red[t + s]); __syncthreads(); }
        if (t == 0) { winner = red[0]; g_nn[round] = (int)(red[0] & 0xffffffffu); }
        __syncthreads();
        unsigned long long wv = winner;
        if (sb[t] == wv) sb[t] = ~0ull;
        if (t < 64 && sb[256 + t] == wv) sb[256 + t] = ~0ull;
        __syncthreads();
    }
}

// ---------------- 9. scalar s ----------------
__global__ void k_scalar(const float* __restrict__ lib, float* __restrict__ out, int write_s) {
    __shared__ float red[6][128];
    int t = threadIdx.x;  // 128
    int sidx = g_sidx, msi = g_mstar_idx;
    int nn[5];
    #pragma unroll
    for (int i = 0; i < 5; i++) nn[i] = g_nn[i];
    float ss[6] = {0.f, 0.f, 0.f, 0.f, 0.f, 0.f};
    #pragma unroll
    for (int j = 0; j < 3; j++) {
        int col = t + 128 * j;
        float p = g_patch_n[sidx * DIM + col];
        float d0 = p - lib[(size_t)msi * DIM + col];
        ss[0] += d0 * d0;
        #pragma unroll
        for (int i = 0; i < 5; i++) {
            float d = p - lib[(size_t)nn[i] * DIM + col];
            ss[1 + i] += d * d;
        }
    }
    #pragma unroll
    for (int q = 0; q < 6; q++) red[q][t] = ss[q];
    __syncthreads();
    for (int s = 64; s > 0; s >>= 1) {
        if (t < s) {
            #pragma unroll
            for (int q = 0; q < 6; q++) red[q][t] += red[q][t + s];
        }
        __syncthreads();
    }
    if (t == 0 && write_s) {
        float num = expf(sqrtf(red[0][0]));
        float den = 0.f;
        #pragma unroll
        for (int i = 0; i < 5; i++) den += expf(sqrtf(red[1 + i][0]));
        out[0] = (1.f - num / den) * g_sstar;
    }
}

// ---------------- 10. bilinear 26 -> 224 ----------------
__global__ void k_upsample() {
    int x = blockIdx.x * 32 + threadIdx.x;
    int y = blockIdx.y * 8 + threadIdx.y;
    if (x >= IMG || y >= IMG) return;
    const float scale = 26.f / 224.f;
    float sx = (x + 0.5f) * scale - 0.5f;
    float sy = (y + 0.5f) * scale - 0.5f;
    int x0 = (int)floorf(sx), y0 = (int)floorf(sy);
    float fx = sx - x0, fy = sy - y0;
    int x0c = min(max(x0, 0), 25), x1c = min(max(x0 + 1, 0), 25);
    int y0c = min(max(y0, 0), 25), y1c = min(max(y0 + 1, 0), 25);
    float v00 = g_minval[y0c * 26 + x0c], v01 = g_minval[y0c * 26 + x1c];
    float v10 = g_minval[y1c * 26 + x0c], v11 = g_minval[y1c * 26 + x1c];
    float top = v00 + fx * (v01 - v00), bot = v10 + fx * (v11 - v10);
    g_map_a[y * IMG + x] = top + fy * (bot - top);
}

__device__ __forceinline__ int reflect_idx(int j) {
    if (j < 0) j = -j;
    if (j > IMG - 1) j = 2 * (IMG - 1) - j;
    return j;
}
__device__ __forceinline__ void blur_weights(float* w) {
    float s = 0.f;
    #pragma unroll
    for (int i = 0; i < 33; i++) {
        float xx = (float)(i - KRAD) / SIGMA;
        w[i] = expf(-0.5f * xx * xx); s += w[i];
    }
    float inv = 1.f / s;
    #pragma unroll
    for (int i = 0; i < 33; i++) w[i] *= inv;
}
__global__ void k_blur_v() {
    int x = blockIdx.x * 32 + threadIdx.x;
    int y = blockIdx.y * 8 + threadIdx.y;
    if (x >= IMG || y >= IMG) return;
    float w[33]; blur_weights(w);
    float acc = 0.f;
    #pragma unroll
    for (int i = 0; i < 33; i++) acc += w[i] * g_map_a[reflect_idx(y + i - KRAD) * IMG + x];
    g_map_b[y * IMG + x] = acc;
}
__global__ void k_blur_h(float* __restrict__ out) {
    int x = blockIdx.x * 32 + threadIdx.x;
    int y = blockIdx.y * 8 + threadIdx.y;
    if (x >= IMG || y >= IMG) return;
    float w[33]; blur_weights(w);
    float acc = 0.f;
    #pragma unroll
    for (int i = 0; i < 33; i++) acc += w[i] * g_map_b[y * IMG + reflect_idx(x + i - KRAD)];
    out[y * IMG + x] = acc;
}

extern "C" void kernel_launch(void* const* d_in, const int* in_sizes, int n_in,
                              void* d_out, int out_size) {
    const float* patch = (const float*)d_in[0];
    const float* lib   = (const float*)d_in[1];
    if (n_in >= 2 && in_sizes[0] != N_PATCH * DIM) {
        patch = (const float*)d_in[1]; lib = (const float*)d_in[0];
    }
    float* out = (float*)d_out;
    int ofs = out_size - IMG * IMG;
    if (ofs < 0) ofs = 0;

    static int smem_set = 0;
    if (!smem_set) {
        cudaFuncSetAttribute(k_main, cudaFuncAttributeMaxDynamicSharedMemorySize, SMEM_MAIN);
        smem_set = 1;
    }

    k_prep_patch<<<NPAD, 128>>>(patch);
    k_prep_lib<<<M_LIB / 8, 256>>>(lib);
    k_init<<<1, 768>>>();
    k_main<<<148, 384, SMEM_MAIN>>>();
    k_nmin<<<1, 1024>>>();
    k_pass2<<<M_LIB / 8, 256>>>();
    k_topscan<<<64, 256>>>();
    k_topfinal<<<1, 256>>>();
    k_scalar<<<1, 128>>>(lib, out, ofs > 0 ? 1 : 0);
    dim3 blk(32, 8), grd(7, 28);
    k_upsample<<<grd, blk>>>();
    k_blur_v<<<grd, blk>>>();
    k_blur_h<<<grd, blk>>>(out + ofs);
}

// round 9
// speedup vs baseline: 1.0352x; 1.0352x over previous
#include <cuda_runtime.h>
#include <cuda_bf16.h>
#include <math.h>
#include <stdint.h>

#define M_LIB   200000
#define N_PATCH 676
#define NPAD    768
#define DIM     384
#define IMG     224
#define SIGMA   4.0f
#define KRAD    16

#define NTILES  43              // 128-row tiles per stripe; 37 stripes
#define STRIPE  (128*NTILES)    // 5504
#define STG_BYTES (128*256)     // one stage: 128 rows x 128 k-elems bf16 (256B pitch)
#define SM_P    0               // patch chunk 192 x 768B = 147456
#define SM_L    147456
#define SM_MIN  (SM_L + 2*STG_BYTES)   // 212992
#define SMEM_MAIN (SM_MIN + 192*8)     // 214528

// ---------------- device scratch ----------------
__device__ __align__(16) __nv_bfloat16 g_lib_bf16[(size_t)M_LIB * DIM];
__device__ float g_ln[M_LIB];
__device__ float g_patch_n[N_PATCH * DIM];
__device__ __align__(16) __nv_bfloat16 g_patch_bf16[NPAD * DIM];
__device__ float g_pn[N_PATCH];
__device__ unsigned long long g_minbuf[NPAD];
__device__ float g_minval[N_PATCH];
__device__ int   g_sidx;
__device__ int   g_mstar_idx;
__device__ float g_sstar;
__device__ float g_d2star[M_LIB];
__device__ unsigned long long g_btop[64 * 5];
__device__ int   g_nn[5];
__device__ float g_map_a[IMG * IMG];
__device__ float g_map_b[IMG * IMG];

// ---------------- helpers ----------------
__device__ __forceinline__ unsigned fordu(float f) {
    unsigned u = __float_as_uint(f);
    return (u & 0x80000000u) ? ~u : (u | 0x80000000u);
}
__device__ __forceinline__ float fordu_inv(unsigned e) {
    return __uint_as_float((e & 0x80000000u) ? (e ^ 0x80000000u) : ~e);
}
__device__ __forceinline__ unsigned long long packkey(float v, int idx) {
    return ((unsigned long long)fordu(v) << 32) | (unsigned)idx;
}
__device__ __forceinline__ unsigned long long ullmin2(unsigned long long a, unsigned long long b) {
    return a < b ? a : b;
}
#define INF_F (__int_as_float(0x7f800000))

__device__ __forceinline__ uint32_t smem_u32(const void* p) {
    return (uint32_t)__cvta_generic_to_shared(p);
}

#define LDSM4(r0,r1,r2,r3,addr) \
    asm volatile("ldmatrix.sync.aligned.m8n8.x4.shared.b16 {%0,%1,%2,%3}, [%4];" \
        : "=r"(r0), "=r"(r1), "=r"(r2), "=r"(r3) : "r"(addr))
#define MMA16816(D,a0,a1,a2,a3,b0,b1) \
    asm volatile("mma.sync.aligned.m16n8k16.row.col.f32.bf16.bf16.f32 " \
        "{%0,%1,%2,%3},{%4,%5,%6,%7},{%8,%9},{%0,%1,%2,%3};" \
        : "+f"((D)[0]), "+f"((D)[1]), "+f"((D)[2]), "+f"((D)[3]) \
        : "r"(a0), "r"(a1), "r"(a2), "r"(a3), "r"(b0), "r"(b1))

__device__ __forceinline__ void cp16(uint32_t dst, const void* src, uint32_t nbytes) {
    asm volatile("cp.async.cg.shared.global [%0], [%1], 16, %2;"
                 :: "r"(dst), "l"(src), "r"(nbytes) : "memory");
}
#define CP_COMMIT() asm volatile("cp.async.commit_group;" ::: "memory")
#define CP_WAIT1()  asm volatile("cp.async.wait_group 1;" ::: "memory")

// ---------------- 1. normalize patch ----------------
__global__ void k_prep_patch(const float* __restrict__ patch) {
    int n = blockIdx.x, t = threadIdx.x;  // 128 thr
    if (n >= N_PATCH) {
        #pragma unroll
        for (int j = 0; j < 3; j++) g_patch_bf16[n * DIM + t + 128 * j] = __float2bfloat16(0.f);
        return;
    }
    __shared__ float red[128];
    float v[3]; float ss = 0.f;
    #pragma unroll
    for (int j = 0; j < 3; j++) { v[j] = patch[(size_t)n * DIM + t + 128 * j]; ss += v[j] * v[j]; }
    red[t] = ss; __syncthreads();
    for (int s = 64; s > 0; s >>= 1) { if (t < s) red[t] += red[t + s]; __syncthreads(); }
    float denom = fmaxf(sqrtf(red[0]), 1e-12f);
    __syncthreads();
    float pn = 0.f;
    #pragma unroll
    for (int j = 0; j < 3; j++) {
        float x = v[j] / denom; pn += x * x;
        g_patch_n[n * DIM + t + 128 * j] = x;
        g_patch_bf16[n * DIM + t + 128 * j] = __float2bfloat16(x);
    }
    red[t] = pn; __syncthreads();
    for (int s = 64; s > 0; s >>= 1) { if (t < s) red[t] += red[t + s]; __syncthreads(); }
    if (t == 0) g_pn[n] = red[0];
}

// ---------------- 2. lib fp32 -> bf16 + ln ----------------
__global__ void k_prep_lib(const float* __restrict__ lib) {
    int w = threadIdx.x >> 5, lane = threadIdx.x & 31;
    int row = blockIdx.x * 8 + w;
    const float4* src = (const float4*)(lib + (size_t)row * DIM);
    __nv_bfloat162* dst = (__nv_bfloat162*)(g_lib_bf16 + (size_t)row * DIM);
    float ss = 0.f;
    #pragma unroll
    for (int j = 0; j < 3; j++) {
        float4 f = src[lane + 32 * j];
        ss += f.x * f.x + f.y * f.y + f.z * f.z + f.w * f.w;
        dst[2 * (lane + 32 * j)]     = __floats2bfloat162_rn(f.x, f.y);
        dst[2 * (lane + 32 * j) + 1] = __floats2bfloat162_rn(f.z, f.w);
    }
    for (int o = 16; o; o >>= 1) ss += __shfl_xor_sync(0xffffffffu, ss, o);
    if (lane == 0) g_ln[row] = ss;
}

__global__ void k_init() {
    for (int i = threadIdx.x; i < NPAD; i += blockDim.x) g_minbuf[i] = ~0ull;
}

// ---------------- 4. fused bf16 HMMA GEMM + per-patch-row max-dot ----------
// grid 148 = 4 n-chunks x 37 stripes; 512 threads = 16 warps as 4 wm x 4 wn.
// CTA tile 128m x 192n, warp tile 32m x 48n: 5 LDSM.x4 per 12 MMA (213 B/MMA).
// Lib streamed as 128-row tiles in 3 k-thirds (256B pitch), 2-stage cp.async.
__global__ void __launch_bounds__(512, 1) k_main() {
    extern __shared__ char sm[];
    const uint32_t smb = smem_u32(sm);
    unsigned long long* sMin = (unsigned long long*)(sm + SM_MIN);
    const int tid = threadIdx.x;
    const int warp = tid >> 5, lane = tid & 31;
    const int nc = blockIdx.x & 3;
    const int mBase = (blockIdx.x >> 2) * STRIPE;

    if (tid < 192) sMin[tid] = ~0ull;

    // --- stage resident patch chunk [192 x 384] bf16, swizzled 768B rows ---
    for (int i = tid; i < 192 * 48; i += 512) {
        int r = i / 48, u = i % 48;
        uint32_t dst = smb + SM_P + r * 768 + (((u ^ (r & 7))) << 4);
        cp16(dst, g_patch_bf16 + (size_t)(nc * 192 + r) * DIM + u * 8, 16);
    }
    CP_COMMIT();

    // --- prologue: stage0 = tile0 third0, stage1 = tile0 third1 ---
    #pragma unroll
    for (int p = 0; p < 2; p++) {
        for (int i = tid; i < 128 * 16; i += 512) {
            int r = i >> 4, u = i & 15;
            int g = mBase + r;
            uint32_t dst = smb + SM_L + p * STG_BYTES + r * 256 + (((u ^ (r & 7))) << 4);
            cp16(dst, g_lib_bf16 + (size_t)min(g, M_LIB - 1) * DIM + p * 128 + u * 8,
                 (g < M_LIB) ? 16u : 0u);
        }
        CP_COMMIT();
    }

    // --- per-thread invariants ---
    const int wm = warp & 3, wn = warp >> 2;      // 4 x 4, warp tile 32m x 48n
    const unsigned hiA = (lane >> 4);
    const unsigned hiB = (lane >> 3) & 1;
    unsigned baseA[2], swA[2];
    #pragma unroll
    for (int mf = 0; mf < 2; mf++) {
        unsigned rA = 32 * wm + 16 * mf + (lane & 15);
        baseA[mf] = rA * 256;
        swA[mf] = rA & 7;
    }
    unsigned pBase[3], swB[3];
    #pragma unroll
    for (int f2 = 0; f2 < 3; f2++) {
        unsigned rB = 48 * wn + 16 * f2 + (lane & 7) + ((lane >> 4) << 3);
        pBase[f2] = smb + SM_P + rB * 768;
        swB[f2] = rB & 7;
    }
    const int g8 = lane >> 2, tig = lane & 3;

    float runV[12]; int runI[12];
    #pragma unroll
    for (int j = 0; j < 12; j++) { runV[j] = -INF_F; runI[j] = 0; }

    float acc[12][4];
    #pragma unroll
    for (int g = 0; g < 12; g++) acc[g][0] = acc[g][1] = acc[g][2] = acc[g][3] = 0.f;

    int s = 0;
    for (int tile = 0; tile < NTILES; tile++) {
        #pragma unroll 1
        for (int q = 0; q < 3; q++) {
            CP_WAIT1();
            __syncthreads();
            // compute this stage: 8 ksteps, 2 A-frags + 3 B-frags, 12 MMAs
            const unsigned stgA = smb + SM_L + s * STG_BYTES;
            const unsigned kq = 16 * q + hiB;
            #pragma unroll
            for (int ks = 0; ks < 8; ks++) {
                unsigned a[2][4];
                unsigned uA = 2 * ks + hiA;
                #pragma unroll
                for (int mf = 0; mf < 2; mf++)
                    LDSM4(a[mf][0], a[mf][1], a[mf][2], a[mf][3],
                          stgA + baseA[mf] + (((uA ^ swA[mf])) << 4));
                unsigned uB = kq + 2 * ks;
                #pragma unroll
                for (int f2 = 0; f2 < 3; f2++) {
                    unsigned r0, r1, r2, r3;
                    LDSM4(r0, r1, r2, r3, pBase[f2] + (((uB ^ swB[f2])) << 4));
                    #pragma unroll
                    for (int mf = 0; mf < 2; mf++) {
                        MMA16816(acc[(mf * 3 + f2) * 2],     a[mf][0], a[mf][1], a[mf][2], a[mf][3], r0, r1);
                        MMA16816(acc[(mf * 3 + f2) * 2 + 1], a[mf][0], a[mf][1], a[mf][2], a[mf][3], r2, r3);
                    }
                }
            }
            __syncthreads();
            // prefetch (tile,q)+2 into this (now free) buffer
            {
                int qN = q + 2, tileN = tile;
                if (qN >= 3) { qN -= 3; tileN++; }
                if (tileN < NTILES) {
                    int mN = mBase + tileN * 128;
                    for (int i = tid; i < 128 * 16; i += 512) {
                        int r = i >> 4, u = i & 15;
                        int g = mN + r;
                        uint32_t dst = smb + SM_L + s * STG_BYTES + r * 256 + (((u ^ (r & 7))) << 4);
                        cp16(dst, g_lib_bf16 + (size_t)min(g, M_LIB - 1) * DIM + qN * 128 + u * 8,
                             (g < M_LIB) ? 16u : 0u);
                    }
                }
                CP_COMMIT();
            }
            s ^= 1;
        }
        // tile epilogue: fold 128-row tile into per-column running max dot
        int mt = mBase + tile * 128;
        #pragma unroll
        for (int g = 0; g < 12; g++) {
            int mf = g / 6;             // g = (mf*3+f2)*2 + nh
            int mlo = mt + 32 * wm + 16 * mf + g8, mhi = mlo + 8;
            bool okLo = mlo < M_LIB, okHi = mhi < M_LIB;
            int jj = g % 6 * 2;         // (f2*2+nh)*2 base for c
            #pragma unroll
            for (int c = 0; c < 2; c++) {
                float vlo = acc[g][c], vhi = acc[g][2 + c];
                if (okLo && vlo > runV[jj + c]) { runV[jj + c] = vlo; runI[jj + c] = mlo; }
                if (okHi && vhi > runV[jj + c]) { runV[jj + c] = vhi; runI[jj + c] = mhi; }
            }
            acc[g][0] = acc[g][1] = acc[g][2] = acc[g][3] = 0.f;
        }
    }

    // reduce over the 8 lanes sharing each column
    #pragma unroll
    for (int off = 4; off < 32; off <<= 1) {
        #pragma unroll
        for (int j = 0; j < 12; j++) {
            float ov = __shfl_xor_sync(0xffffffffu, runV[j], off);
            int   oi = __shfl_xor_sync(0xffffffffu, runI[j], off);
            if (ov > runV[j]) { runV[j] = ov; runI[j] = oi; }
        }
    }
    if (g8 == 0) {
        #pragma unroll
        for (int jj = 0; jj < 12; jj++) {
            int f2 = jj >> 2, nh = (jj >> 1) & 1, c = jj & 1;
            int col = 48 * wn + 16 * f2 + 8 * nh + 2 * tig + c;
            atomicMin(&sMin[col], packkey(-runV[jj], runI[jj]));
        }
    }
    __syncthreads();
    if (tid < 192) atomicMin(&g_minbuf[nc * 192 + tid], sMin[tid]);
}

// ---------------- 5. min_val per n + argmax over n ----------------
__global__ void k_nmin() {
    int t = threadIdx.x;  // 1024
    __shared__ float rv[1024]; __shared__ int ri[1024];
    float mv = -INF_F; int idx = 0;
    if (t < N_PATCH) {
        unsigned long long key = g_minbuf[t];
        int mi = (int)(key & 0xffffffffu);
        float v = fordu_inv((unsigned)(key >> 32));   // = -max_dot
        float d2 = g_pn[t] + g_ln[mi] + 2.f * v;
        mv = sqrtf(fmaxf(d2, 0.f));
        g_minval[t] = mv; idx = t;
    }
    rv[t] = mv; ri[t] = idx; __syncthreads();
    for (int s = 512; s > 0; s >>= 1) {
        if (t < s && rv[t + s] > rv[t]) { rv[t] = rv[t + s]; ri[t] = ri[t + s]; }
        __syncthreads();
    }
    if (t == 0) {
        g_sidx = ri[0]; g_sstar = rv[0];
        g_mstar_idx = (int)(g_minbuf[ri[0]] & 0xffffffffu);
    }
}

// ---------------- 6. d*^2 (shifted) over all lib rows ----------------
__global__ void k_pass2() {
    int w = threadIdx.x >> 5, lane = threadIdx.x & 31;
    int row = blockIdx.x * 8 + w;
    int msi = g_mstar_idx;
    const unsigned* a = (const unsigned*)(g_lib_bf16 + (size_t)row * DIM);
    const unsigned* b = (const unsigned*)(g_lib_bf16 + (size_t)msi * DIM);
    float dot = 0.f;
    #pragma unroll
    for (int j = 0; j < 6; j++) {
        unsigned ua = a[lane + 32 * j], ub = b[lane + 32 * j];
        float2 fa = __bfloat1622float2(*(__nv_bfloat162*)&ua);
        float2 fb = __bfloat1622float2(*(__nv_bfloat162*)&ub);
        dot = fmaf(fa.x, fb.x, dot); dot = fmaf(fa.y, fb.y, dot);
    }
    for (int o = 16; o; o >>= 1) dot += __shfl_xor_sync(0xffffffffu, dot, o);
    if (lane == 0) g_d2star[row] = g_ln[row] - 2.f * dot;
}

// ---------------- 7. top-5 smallest, block stage ----------------
__global__ void k_topscan() {
    unsigned long long best[5];
    #pragma unroll
    for (int r = 0; r < 5; r++) best[r] = ~0ull;
    for (int m = blockIdx.x * 256 + threadIdx.x; m < M_LIB; m += 64 * 256) {
        unsigned long long key = packkey(g_d2star[m], m);
        if (key < best[4]) {
            best[4] = key;
            #pragma unroll
            for (int r = 4; r > 0; r--)
                if (best[r] < best[r - 1]) { unsigned long long tm = best[r]; best[r] = best[r - 1]; best[r - 1] = tm; }
        }
    }
    __shared__ unsigned long long sb[5 * 256], red[256], winner;
    int t = threadIdx.x;
    #pragma unroll
    for (int r = 0; r < 5; r++) sb[r * 256 + t] = best[r];
    __syncthreads();
    for (int round = 0; round < 5; round++) {
        unsigned long long mn = ~0ull;
        #pragma unroll
        for (int r = 0; r < 5; r++) mn = ullmin2(mn, sb[r * 256 + t]);
        red[t] = mn; __syncthreads();
        for (int s = 128; s > 0; s >>= 1) { if (t < s) red[t] = ullmin2(red[t], red[t + s]); __syncthreads(); }
        if (t == 0) { winner = red[0]; g_btop[blockIdx.x * 5 + round] = red[0]; }
        __syncthreads();
        unsigned long long wv = winner;
        #pragma unroll
        for (int r = 0; r < 5; r++) if (sb[r * 256 + t] == wv) sb[r * 256 + t] = ~0ull;
        __syncthreads();
    }
}

// ---------------- 8. top-5 final merge ----------------
__global__ void k_topfinal() {
    __shared__ unsigned long long sb[320], red[256], winner;
    int t = threadIdx.x;  // 256
    sb[t] = g_btop[t];
    if (t < 64) sb[256 + t] = g_btop[256 + t];
    __syncthreads();
    for (int round = 0; round < 5; round++) {
        unsigned long long mn = sb[t];
        if (t < 64) mn = ullmin2(mn, sb[256 + t]);
        red[t] = mn; __syncthreads();
        for (int s = 128; s > 0; s >>= 1) { if (t < s) red[t] = ullmin2(red[t], red[t + s]); __syncthreads(); }
        if (t == 0) { winner = red[0]; g_nn[round] = (int)(red[0] & 0xffffffffu); }
        __syncthreads();
        unsigned long long wv = winner;
        if (sb[t] == wv) sb[t] = ~0ull;
        if (t < 64 && sb[256 + t] == wv) sb[256 + t] = ~0ull;
        __syncthreads();
    }
}

// ---------------- 9. scalar s ----------------
__global__ void k_scalar(const float* __restrict__ lib, float* __restrict__ out, int write_s) {
    __shared__ float red[6][128];
    int t = threadIdx.x;  // 128
    int sidx = g_sidx, msi = g_mstar_idx;
    int nn[5];
    #pragma unroll
    for (int i = 0; i < 5; i++) nn[i] = g_nn[i];
    float ss[6] = {0.f, 0.f, 0.f, 0.f, 0.f, 0.f};
    #pragma unroll
    for (int j = 0; j < 3; j++) {
        int col = t + 128 * j;
        float p = g_patch_n[sidx * DIM + col];
        float d0 = p - lib[(size_t)msi * DIM + col];
        ss[0] += d0 * d0;
        #pragma unroll
        for (int i = 0; i < 5; i++) {
            float d = p - lib[(size_t)nn[i] * DIM + col];
            ss[1 + i] += d * d;
        }
    }
    #pragma unroll
    for (int q = 0; q < 6; q++) red[q][t] = ss[q];
    __syncthreads();
    for (int s = 64; s > 0; s >>= 1) {
        if (t < s) {
            #pragma unroll
            for (int q = 0; q < 6; q++) red[q][t] += red[q][t + s];
        }
        __syncthreads();
    }
    if (t == 0 && write_s) {
        float num = expf(sqrtf(red[0][0]));
        float den = 0.f;
        #pragma unroll
        for (int i = 0; i < 5; i++) den += expf(sqrtf(red[1 + i][0]));
        out[0] = (1.f - num / den) * g_sstar;
    }
}

// ---------------- 10. bilinear 26 -> 224 ----------------
__global__ void k_upsample() {
    int x = blockIdx.x * 32 + threadIdx.x;
    int y = blockIdx.y * 8 + threadIdx.y;
    if (x >= IMG || y >= IMG) return;
    const float scale = 26.f / 224.f;
    float sx = (x + 0.5f) * scale - 0.5f;
    float sy = (y + 0.5f) * scale - 0.5f;
    int x0 = (int)floorf(sx), y0 = (int)floorf(sy);
    float fx = sx - x0, fy = sy - y0;
    int x0c = min(max(x0, 0), 25), x1c = min(max(x0 + 1, 0), 25);
    int y0c = min(max(y0, 0), 25), y1c = min(max(y0 + 1, 0), 25);
    float v00 = g_minval[y0c * 26 + x0c], v01 = g_minval[y0c * 26 + x1c];
    float v10 = g_minval[y1c * 26 + x0c], v11 = g_minval[y1c * 26 + x1c];
    float top = v00 + fx * (v01 - v00), bot = v10 + fx * (v11 - v10);
    g_map_a[y * IMG + x] = top + fy * (bot - top);
}

__device__ __forceinline__ int reflect_idx(int j) {
    if (j < 0) j = -j;
    if (j > IMG - 1) j = 2 * (IMG - 1) - j;
    return j;
}
__device__ __forceinline__ void blur_weights(float* w) {
    float s = 0.f;
    #pragma unroll
    for (int i = 0; i < 33; i++) {
        float xx = (float)(i - KRAD) / SIGMA;
        w[i] = expf(-0.5f * xx * xx); s += w[i];
    }
    float inv = 1.f / s;
    #pragma unroll
    for (int i = 0; i < 33; i++) w[i] *= inv;
}
__global__ void k_blur_v() {
    int x = blockIdx.x * 32 + threadIdx.x;
    int y = blockIdx.y * 8 + threadIdx.y;
    if (x >= IMG || y >= IMG) return;
    float w[33]; blur_weights(w);
    float acc = 0.f;
    #pragma unroll
    for (int i = 0; i < 33; i++) acc += w[i] * g_map_a[reflect_idx(y + i - KRAD) * IMG + x];
    g_map_b[y * IMG + x] = acc;
}
__global__ void k_blur_h(float* __restrict__ out) {
    int x = blockIdx.x * 32 + threadIdx.x;
    int y = blockIdx.y * 8 + threadIdx.y;
    if (x >= IMG || y >= IMG) return;
    float w[33]; blur_weights(w);
    float acc = 0.f;
    #pragma unroll
    for (int i = 0; i < 33; i++) acc += w[i] * g_map_b[y * IMG + reflect_idx(x + i - KRAD)];
    out[y * IMG + x] = acc;
}

extern "C" void kernel_launch(void* const* d_in, const int* in_sizes, int n_in,
                              void* d_out, int out_size) {
    const float* patch = (const float*)d_in[0];
    const float* lib   = (const float*)d_in[1];
    if (n_in >= 2 && in_sizes[0] != N_PATCH * DIM) {
        patch = (const float*)d_in[1]; lib = (const float*)d_in[0];
    }
    float* out = (float*)d_out;
    int ofs = out_size - IMG * IMG;
    if (ofs < 0) ofs = 0;

    static int smem_set = 0;
    if (!smem_set) {
        cudaFuncSetAttribute(k_main, cudaFuncAttributeMaxDynamicSharedMemorySize, SMEM_MAIN);
        smem_set = 1;
    }

    k_prep_patch<<<NPAD, 128>>>(patch);
    k_prep_lib<<<M_LIB / 8, 256>>>(lib);
    k_init<<<1, 768>>>();
    k_main<<<148, 512, SMEM_MAIN>>>();
    k_nmin<<<1, 1024>>>();
    k_pass2<<<M_LIB / 8, 256>>>();
    k_topscan<<<64, 256>>>();
    k_topfinal<<<1, 256>>>();
    k_scalar<<<1, 128>>>(lib, out, ofs > 0 ? 1 : 0);
    dim3 blk(32, 8), grd(7, 28);
    k_upsample<<<grd, blk>>>();
    k_blur_v<<<grd, blk>>>();
    k_blur_h<<<grd, blk>>>(out + ofs);
}

// round 10
// speedup vs baseline: 1.0385x; 1.0032x over previous
#include <cuda_runtime.h>
#include <cuda_bf16.h>
#include <math.h>
#include <stdint.h>

#define M_LIB   200000
#define N_PATCH 676
#define NPAD    768
#define DIM     384
#define IMG     224
#define SIGMA   4.0f
#define KRAD    16

#define NTILES  43              // 128-row tiles per stripe; 37 stripes
#define STRIPE  (128*NTILES)    // 5504
#define NITER   (NTILES*6)      // 258 k-sixth stages
#define STG_BYTES (128*128)     // one stage: 128 rows x 64 k-elems bf16 (128B pitch)
#define SM_P    0               // patch chunk 192 x 768B = 147456
#define SM_L    147456
#define SM_MIN  (SM_L + 3*STG_BYTES)   // 196608
#define SMEM_MAIN (SM_MIN + 192*8)     // 198144

// ---------------- device scratch ----------------
__device__ __align__(16) __nv_bfloat16 g_lib_bf16[(size_t)M_LIB * DIM];
__device__ float g_ln[M_LIB];
__device__ float g_patch_n[N_PATCH * DIM];
__device__ __align__(16) __nv_bfloat16 g_patch_bf16[NPAD * DIM];
__device__ float g_pn[N_PATCH];
__device__ unsigned long long g_minbuf[NPAD];
__device__ float g_minval[N_PATCH];
__device__ int   g_sidx;
__device__ int   g_mstar_idx;
__device__ float g_sstar;
__device__ float g_d2star[M_LIB];
__device__ unsigned long long g_btop[64 * 5];
__device__ int   g_nn[5];
__device__ float g_map_a[IMG * IMG];
__device__ float g_map_b[IMG * IMG];

// ---------------- helpers ----------------
__device__ __forceinline__ unsigned fordu(float f) {
    unsigned u = __float_as_uint(f);
    return (u & 0x80000000u) ? ~u : (u | 0x80000000u);
}
__device__ __forceinline__ float fordu_inv(unsigned e) {
    return __uint_as_float((e & 0x80000000u) ? (e ^ 0x80000000u) : ~e);
}
__device__ __forceinline__ unsigned long long packkey(float v, int idx) {
    return ((unsigned long long)fordu(v) << 32) | (unsigned)idx;
}
__device__ __forceinline__ unsigned long long ullmin2(unsigned long long a, unsigned long long b) {
    return a < b ? a : b;
}
#define INF_F (__int_as_float(0x7f800000))

__device__ __forceinline__ uint32_t smem_u32(const void* p) {
    return (uint32_t)__cvta_generic_to_shared(p);
}

#define LDSM4(r0,r1,r2,r3,addr) \
    asm volatile("ldmatrix.sync.aligned.m8n8.x4.shared.b16 {%0,%1,%2,%3}, [%4];" \
        : "=r"(r0), "=r"(r1), "=r"(r2), "=r"(r3) : "r"(addr))
#define MMA16816(D,a0,a1,a2,a3,b0,b1) \
    asm volatile("mma.sync.aligned.m16n8k16.row.col.f32.bf16.bf16.f32 " \
        "{%0,%1,%2,%3},{%4,%5,%6,%7},{%8,%9},{%0,%1,%2,%3};" \
        : "+f"((D)[0]), "+f"((D)[1]), "+f"((D)[2]), "+f"((D)[3]) \
        : "r"(a0), "r"(a1), "r"(a2), "r"(a3), "r"(b0), "r"(b1))

__device__ __forceinline__ void cp16(uint32_t dst, const void* src, uint32_t nbytes) {
    asm volatile("cp.async.cg.shared.global [%0], [%1], 16, %2;"
                 :: "r"(dst), "l"(src), "r"(nbytes) : "memory");
}
#define CP_COMMIT() asm volatile("cp.async.commit_group;" ::: "memory")
#define CP_WAIT1()  asm volatile("cp.async.wait_group 1;" ::: "memory")

// ---------------- 1. normalize patch (+ minbuf init in padding blocks) ----
__global__ void k_prep_patch(const float* __restrict__ patch) {
    int n = blockIdx.x, t = threadIdx.x;  // 128 thr
    if (n >= N_PATCH) {
        #pragma unroll
        for (int j = 0; j < 3; j++) g_patch_bf16[n * DIM + t + 128 * j] = __float2bfloat16(0.f);
        int idx = (n - N_PATCH) * 128 + t;
        if (idx < NPAD) g_minbuf[idx] = ~0ull;
        return;
    }
    __shared__ float red[128];
    float v[3]; float ss = 0.f;
    #pragma unroll
    for (int j = 0; j < 3; j++) { v[j] = patch[(size_t)n * DIM + t + 128 * j]; ss += v[j] * v[j]; }
    red[t] = ss; __syncthreads();
    for (int s = 64; s > 0; s >>= 1) { if (t < s) red[t] += red[t + s]; __syncthreads(); }
    float denom = fmaxf(sqrtf(red[0]), 1e-12f);
    __syncthreads();
    float pn = 0.f;
    #pragma unroll
    for (int j = 0; j < 3; j++) {
        float x = v[j] / denom; pn += x * x;
        g_patch_n[n * DIM + t + 128 * j] = x;
        g_patch_bf16[n * DIM + t + 128 * j] = __float2bfloat16(x);
    }
    red[t] = pn; __syncthreads();
    for (int s = 64; s > 0; s >>= 1) { if (t < s) red[t] += red[t + s]; __syncthreads(); }
    if (t == 0) g_pn[n] = red[0];
}

// ---------------- 2. lib fp32 -> bf16 + ln ----------------
__global__ void k_prep_lib(const float* __restrict__ lib) {
    int w = threadIdx.x >> 5, lane = threadIdx.x & 31;
    int row = blockIdx.x * 8 + w;
    const float4* src = (const float4*)(lib + (size_t)row * DIM);
    __nv_bfloat162* dst = (__nv_bfloat162*)(g_lib_bf16 + (size_t)row * DIM);
    float ss = 0.f;
    #pragma unroll
    for (int j = 0; j < 3; j++) {
        float4 f = src[lane + 32 * j];
        ss += f.x * f.x + f.y * f.y + f.z * f.z + f.w * f.w;
        dst[2 * (lane + 32 * j)]     = __floats2bfloat162_rn(f.x, f.y);
        dst[2 * (lane + 32 * j) + 1] = __floats2bfloat162_rn(f.z, f.w);
    }
    for (int o = 16; o; o >>= 1) ss += __shfl_xor_sync(0xffffffffu, ss, o);
    if (lane == 0) g_ln[row] = ss;
}

// ---------------- 4. fused bf16 HMMA GEMM + per-patch-row max-dot ----------
// grid 148 = 4 n-chunks x 37 stripes; 512 threads = 16 warps as 4 wm x 4 wn.
// CTA tile 128m x 192n, warp tile 32m x 48n (5 LDSM.x4 / 12 MMA, 213 B/MMA).
// Lib streamed as 128-row tiles in 6 k-sixths (128B pitch), 3-stage cp.async,
// ONE __syncthreads per stage, prefetch issued before compute.
__global__ void __launch_bounds__(512, 1) k_main() {
    extern __shared__ char sm[];
    const uint32_t smb = smem_u32(sm);
    unsigned long long* sMin = (unsigned long long*)(sm + SM_MIN);
    const int tid = threadIdx.x;
    const int warp = tid >> 5, lane = tid & 31;
    const int nc = blockIdx.x & 3;
    const int mBase = (blockIdx.x >> 2) * STRIPE;

    if (tid < 192) sMin[tid] = ~0ull;

    // --- stage resident patch chunk [192 x 384] bf16, swizzled 768B rows ---
    for (int i = tid; i < 192 * 48; i += 512) {
        int r = i / 48, u = i % 48;
        uint32_t dst = smb + SM_P + r * 768 + (((u ^ (r & 7))) << 4);
        cp16(dst, g_patch_bf16 + (size_t)(nc * 192 + r) * DIM + u * 8, 16);
    }
    // --- prologue: stage0 (group with patch), stage1 ---
    const int pr = tid >> 3, pu = tid & 7;          // rows via tid, 2 per thread
    const int pr2 = pr + 64;
    #pragma unroll
    for (int p = 0; p < 2; p++) {
        int g1 = mBase + pr, g2 = mBase + pr2;
        cp16(smb + SM_L + p * STG_BYTES + pr * 128 + (((pu ^ (pr & 7))) << 4),
             g_lib_bf16 + (size_t)min(g1, M_LIB - 1) * DIM + p * 64 + pu * 8,
             (g1 < M_LIB) ? 16u : 0u);
        cp16(smb + SM_L + p * STG_BYTES + pr2 * 128 + (((pu ^ (pr2 & 7))) << 4),
             g_lib_bf16 + (size_t)min(g2, M_LIB - 1) * DIM + p * 64 + pu * 8,
             (g2 < M_LIB) ? 16u : 0u);
        CP_COMMIT();
    }

    // --- per-thread invariants ---
    const int wm = warp & 3, wn = warp >> 2;      // 4 x 4, warp tile 32m x 48n
    const unsigned hiA = (lane >> 4);
    const unsigned hiB = (lane >> 3) & 1;
    unsigned baseA[2], swA[2];
    #pragma unroll
    for (int mf = 0; mf < 2; mf++) {
        unsigned rA = 32 * wm + 16 * mf + (lane & 15);
        baseA[mf] = rA * 128;
        swA[mf] = rA & 7;
    }
    unsigned pBase[3], swB[3];
    #pragma unroll
    for (int f2 = 0; f2 < 3; f2++) {
        unsigned rB = 48 * wn + 16 * f2 + (lane & 7) + ((lane >> 4) << 3);
        pBase[f2] = smb + SM_P + rB * 768;
        swB[f2] = rB & 7;
    }
    const int g8 = lane >> 2, tig = lane & 3;

    float runV[12]; int runI[12];
    #pragma unroll
    for (int j = 0; j < 12; j++) { runV[j] = -INF_F; runI[j] = 0; }

    float acc[12][4];
    #pragma unroll
    for (int g = 0; g < 12; g++) acc[g][0] = acc[g][1] = acc[g][2] = acc[g][3] = 0.f;

    int s = 0;        // buffer for stage i
    int q = 0;        // i % 6
    int tile = 0;
    for (int i = 0; i < NITER; i++) {
        CP_WAIT1();
        __syncthreads();
        // issue prefetch for stage i+2 into buf (s+2)%3 (freed by compute(i-1))
        {
            int nx = i + 2;
            if (nx < NITER) {
                int sN = s + 2; if (sN >= 3) sN -= 3;
                int tN = nx / 6, qN = nx - tN * 6;
                int mN = mBase + tN * 128;
                int g1 = mN + pr, g2 = mN + pr2;
                const __nv_bfloat16* srcb = g_lib_bf16 + (size_t)qN * 64;
                cp16(smb + SM_L + sN * STG_BYTES + pr * 128 + (((pu ^ (pr & 7))) << 4),
                     srcb + (size_t)min(g1, M_LIB - 1) * DIM + pu * 8,
                     (g1 < M_LIB) ? 16u : 0u);
                cp16(smb + SM_L + sN * STG_BYTES + pr2 * 128 + (((pu ^ (pr2 & 7))) << 4),
                     srcb + (size_t)min(g2, M_LIB - 1) * DIM + pu * 8,
                     (g2 < M_LIB) ? 16u : 0u);
            }
            CP_COMMIT();
        }
        // compute stage i: 4 ksteps, 2 A-frags + 3 B-frags, 12 MMAs each
        const unsigned stgA = smb + SM_L + s * STG_BYTES;
        const unsigned pq = q * 128;
        #pragma unroll
        for (int ks = 0; ks < 4; ks++) {
            unsigned a[2][4];
            unsigned uA = 2 * ks + hiA;
            #pragma unroll
            for (int mf = 0; mf < 2; mf++)
                LDSM4(a[mf][0], a[mf][1], a[mf][2], a[mf][3],
                      stgA + baseA[mf] + (((uA ^ swA[mf])) << 4));
            unsigned uB = hiB + 2 * ks;
            #pragma unroll
            for (int f2 = 0; f2 < 3; f2++) {
                unsigned r0, r1, r2, r3;
                LDSM4(r0, r1, r2, r3, pBase[f2] + pq + (((uB ^ swB[f2])) << 4));
                #pragma unroll
                for (int mf = 0; mf < 2; mf++) {
                    MMA16816(acc[(mf * 3 + f2) * 2],     a[mf][0], a[mf][1], a[mf][2], a[mf][3], r0, r1);
                    MMA16816(acc[(mf * 3 + f2) * 2 + 1], a[mf][0], a[mf][1], a[mf][2], a[mf][3], r2, r3);
                }
            }
        }
        s++; if (s == 3) s = 0;
        q++;
        if (q == 6) {
            q = 0;
            // tile epilogue: fold 128-row tile into per-column running max dot
            int mt = mBase + tile * 128;
            #pragma unroll
            for (int g = 0; g < 12; g++) {
                int mf = g / 6;
                int mlo = mt + 32 * wm + 16 * mf + g8, mhi = mlo + 8;
                bool okLo = mlo < M_LIB, okHi = mhi < M_LIB;
                int jj = (g % 6) * 2;
                #pragma unroll
                for (int c = 0; c < 2; c++) {
                    float vlo = acc[g][c], vhi = acc[g][2 + c];
                    if (okLo && vlo > runV[jj + c]) { runV[jj + c] = vlo; runI[jj + c] = mlo; }
                    if (okHi && vhi > runV[jj + c]) { runV[jj + c] = vhi; runI[jj + c] = mhi; }
                }
                acc[g][0] = acc[g][1] = acc[g][2] = acc[g][3] = 0.f;
            }
            tile++;
        }
    }

    // reduce over the 8 lanes sharing each column
    #pragma unroll
    for (int off = 4; off < 32; off <<= 1) {
        #pragma unroll
        for (int j = 0; j < 12; j++) {
            float ov = __shfl_xor_sync(0xffffffffu, runV[j], off);
            int   oi = __shfl_xor_sync(0xffffffffu, runI[j], off);
            if (ov > runV[j]) { runV[j] = ov; runI[j] = oi; }
        }
    }
    if (g8 == 0) {
        #pragma unroll
        for (int jj = 0; jj < 12; jj++) {
            int f2 = jj >> 2, nh = (jj >> 1) & 1, c = jj & 1;
            int col = 48 * wn + 16 * f2 + 8 * nh + 2 * tig + c;
            atomicMin(&sMin[col], packkey(-runV[jj], runI[jj]));
        }
    }
    __syncthreads();
    if (tid < 192) atomicMin(&g_minbuf[nc * 192 + tid], sMin[tid]);
}

// ---------------- 5. min_val per n + argmax over n ----------------
__global__ void k_nmin() {
    int t = threadIdx.x;  // 1024
    __shared__ float rv[1024]; __shared__ int ri[1024];
    float mv = -INF_F; int idx = 0;
    if (t < N_PATCH) {
        unsigned long long key = g_minbuf[t];
        int mi = (int)(key & 0xffffffffu);
        float v = fordu_inv((unsigned)(key >> 32));   // = -max_dot
        float d2 = g_pn[t] + g_ln[mi] + 2.f * v;
        mv = sqrtf(fmaxf(d2, 0.f));
        g_minval[t] = mv; idx = t;
    }
    rv[t] = mv; ri[t] = idx; __syncthreads();
    for (int s = 512; s > 0; s >>= 1) {
        if (t < s && rv[t + s] > rv[t]) { rv[t] = rv[t + s]; ri[t] = ri[t + s]; }
        __syncthreads();
    }
    if (t == 0) {
        g_sidx = ri[0]; g_sstar = rv[0];
        g_mstar_idx = (int)(g_minbuf[ri[0]] & 0xffffffffu);
    }
}

// ---------------- 6. d*^2 (shifted) over all lib rows ----------------
__global__ void k_pass2() {
    int w = threadIdx.x >> 5, lane = threadIdx.x & 31;
    int row = blockIdx.x * 8 + w;
    int msi = g_mstar_idx;
    const unsigned* a = (const unsigned*)(g_lib_bf16 + (size_t)row * DIM);
    const unsigned* b = (const unsigned*)(g_lib_bf16 + (size_t)msi * DIM);
    float dot = 0.f;
    #pragma unroll
    for (int j = 0; j < 6; j++) {
        unsigned ua = a[lane + 32 * j], ub = b[lane + 32 * j];
        float2 fa = __bfloat1622float2(*(__nv_bfloat162*)&ua);
        float2 fb = __bfloat1622float2(*(__nv_bfloat162*)&ub);
        dot = fmaf(fa.x, fb.x, dot); dot = fmaf(fa.y, fb.y, dot);
    }
    for (int o = 16; o; o >>= 1) dot += __shfl_xor_sync(0xffffffffu, dot, o);
    if (lane == 0) g_d2star[row] = g_ln[row] - 2.f * dot;
}

// ---------------- 7. top-5 smallest, block stage ----------------
__global__ void k_topscan() {
    unsigned long long best[5];
    #pragma unroll
    for (int r = 0; r < 5; r++) best[r] = ~0ull;
    for (int m = blockIdx.x * 256 + threadIdx.x; m < M_LIB; m += 64 * 256) {
        unsigned long long key = packkey(g_d2star[m], m);
        if (key < best[4]) {
            best[4] = key;
            #pragma unroll
            for (int r = 4; r > 0; r--)
                if (best[r] < best[r - 1]) { unsigned long long tm = best[r]; best[r] = best[r - 1]; best[r - 1] = tm; }
        }
    }
    __shared__ unsigned long long sb[5 * 256], red[256], winner;
    int t = threadIdx.x;
    #pragma unroll
    for (int r = 0; r < 5; r++) sb[r * 256 + t] = best[r];
    __syncthreads();
    for (int round = 0; round < 5; round++) {
        unsigned long long mn = ~0ull;
        #pragma unroll
        for (int r = 0; r < 5; r++) mn = ullmin2(mn, sb[r * 256 + t]);
        red[t] = mn; __syncthreads();
        for (int s = 128; s > 0; s >>= 1) { if (t < s) red[t] = ullmin2(red[t], red[t + s]); __syncthreads(); }
        if (t == 0) { winner = red[0]; g_btop[blockIdx.x * 5 + round] = red[0]; }
        __syncthreads();
        unsigned long long wv = winner;
        #pragma unroll
        for (int r = 0; r < 5; r++) if (sb[r * 256 + t] == wv) sb[r * 256 + t] = ~0ull;
        __syncthreads();
    }
}

// ---------------- 8. top-5 final merge ----------------
__global__ void k_topfinal() {
    __shared__ unsigned long long sb[320], red[256], winner;
    int t = threadIdx.x;  // 256
    sb[t] = g_btop[t];
    if (t < 64) sb[256 + t] = g_btop[256 + t];
    __syncthreads();
    for (int round = 0; round < 5; round++) {
        unsigned long long mn = sb[t];
        if (t < 64) mn = ullmin2(mn, sb[256 + t]);
        red[t] = mn; __syncthreads();
        for (int s = 128; s > 0; s >>= 1) { if (t < s) red[t] = ullmin2(red[t], red[t + s]); __syncthreads(); }
        if (t == 0) { winner = red[0]; g_nn[round] = (int)(red[0] & 0xffffffffu); }
        __syncthreads();
        unsigned long long wv = winner;
        if (sb[t] == wv) sb[t] = ~0ull;
        if (t < 64 && sb[256 + t] == wv) sb[256 + t] = ~0ull;
        __syncthreads();
    }
}

// ---------------- 9. scalar s ----------------
__global__ void k_scalar(const float* __restrict__ lib, float* __restrict__ out, int write_s) {
    __shared__ float red[6][128];
    int t = threadIdx.x;  // 128
    int sidx = g_sidx, msi = g_mstar_idx;
    int nn[5];
    #pragma unroll
    for (int i = 0; i < 5; i++) nn[i] = g_nn[i];
    float ss[6] = {0.f, 0.f, 0.f, 0.f, 0.f, 0.f};
    #pragma unroll
    for (int j = 0; j < 3; j++) {
        int col = t + 128 * j;
        float p = g_patch_n[sidx * DIM + col];
        float d0 = p - lib[(size_t)msi * DIM + col];
        ss[0] += d0 * d0;
        #pragma unroll
        for (int i = 0; i < 5; i++) {
            float d = p - lib[(size_t)nn[i] * DIM + col];
            ss[1 + i] += d * d;
        }
    }
    #pragma unroll
    for (int q = 0; q < 6; q++) red[q][t] = ss[q];
    __syncthreads();
    for (int s = 64; s > 0; s >>= 1) {
        if (t < s) {
            #pragma unroll
            for (int q = 0; q < 6; q++) red[q][t] += red[q][t + s];
        }
        __syncthreads();
    }
    if (t == 0 && write_s) {
        float num = expf(sqrtf(red[0][0]));
        float den = 0.f;
        #pragma unroll
        for (int i = 0; i < 5; i++) den += expf(sqrtf(red[1 + i][0]));
        out[0] = (1.f - num / den) * g_sstar;
    }
}

// ---------------- 10. bilinear 26 -> 224 ----------------
__global__ void k_upsample() {
    int x = blockIdx.x * 32 + threadIdx.x;
    int y = blockIdx.y * 8 + threadIdx.y;
    if (x >= IMG || y >= IMG) return;
    const float scale = 26.f / 224.f;
    float sx = (x + 0.5f) * scale - 0.5f;
    float sy = (y + 0.5f) * scale - 0.5f;
    int x0 = (int)floorf(sx), y0 = (int)floorf(sy);
    float fx = sx - x0, fy = sy - y0;
    int x0c = min(max(x0, 0), 25), x1c = min(max(x0 + 1, 0), 25);
    int y0c = min(max(y0, 0), 25), y1c = min(max(y0 + 1, 0), 25);
    float v00 = g_minval[y0c * 26 + x0c], v01 = g_minval[y0c * 26 + x1c];
    float v10 = g_minval[y1c * 26 + x0c], v11 = g_minval[y1c * 26 + x1c];
    float top = v00 + fx * (v01 - v00), bot = v10 + fx * (v11 - v10);
    g_map_a[y * IMG + x] = top + fy * (bot - top);
}

__device__ __forceinline__ int reflect_idx(int j) {
    if (j < 0) j = -j;
    if (j > IMG - 1) j = 2 * (IMG - 1) - j;
    return j;
}
__device__ __forceinline__ void blur_weights(float* w) {
    float s = 0.f;
    #pragma unroll
    for (int i = 0; i < 33; i++) {
        float xx = (float)(i - KRAD) / SIGMA;
        w[i] = expf(-0.5f * xx * xx); s += w[i];
    }
    float inv = 1.f / s;
    #pragma unroll
    for (int i = 0; i < 33; i++) w[i] *= inv;
}
__global__ void k_blur_v() {
    int x = blockIdx.x * 32 + threadIdx.x;
    int y = blockIdx.y * 8 + threadIdx.y;
    if (x >= IMG || y >= IMG) return;
    float w[33]; blur_weights(w);
    float acc = 0.f;
    #pragma unroll
    for (int i = 0; i < 33; i++) acc += w[i] * g_map_a[reflect_idx(y + i - KRAD) * IMG + x];
    g_map_b[y * IMG + x] = acc;
}
__global__ void k_blur_h(float* __restrict__ out) {
    int x = blockIdx.x * 32 + threadIdx.x;
    int y = blockIdx.y * 8 + threadIdx.y;
    if (x >= IMG || y >= IMG) return;
    float w[33]; blur_weights(w);
    float acc = 0.f;
    #pragma unroll
    for (int i = 0; i < 33; i++) acc += w[i] * g_map_b[y * IMG + reflect_idx(x + i - KRAD)];
    out[y * IMG + x] = acc;
}

extern "C" void kernel_launch(void* const* d_in, const int* in_sizes, int n_in,
                              void* d_out, int out_size) {
    const float* patch = (const float*)d_in[0];
    const float* lib   = (const float*)d_in[1];
    if (n_in >= 2 && in_sizes[0] != N_PATCH * DIM) {
        patch = (const float*)d_in[1]; lib = (const float*)d_in[0];
    }
    float* out = (float*)d_out;
    int ofs = out_size - IMG * IMG;
    if (ofs < 0) ofs = 0;

    static int smem_set = 0;
    if (!smem_set) {
        cudaFuncSetAttribute(k_main, cudaFuncAttributeMaxDynamicSharedMemorySize, SMEM_MAIN);
        smem_set = 1;
    }

    k_prep_patch<<<NPAD, 128>>>(patch);
    k_prep_lib<<<M_LIB / 8, 256>>>(lib);
    k_main<<<148, 512, SMEM_MAIN>>>();
    k_nmin<<<1, 1024>>>();
    k_pass2<<<M_LIB / 8, 256>>>();
    k_topscan<<<64, 256>>>();
    k_topfinal<<<1, 256>>>();
    k_scalar<<<1, 128>>>(lib, out, ofs > 0 ? 1 : 0);
    dim3 blk(32, 8), grd(7, 28);
    k_upsample<<<grd, blk>>>();
    k_blur_v<<<grd, blk>>>();
    k_blur_h<<<grd, blk>>>(out + ofs);
}

// round 11
// speedup vs baseline: 1.0543x; 1.0152x over previous
#include <cuda_runtime.h>
#include <cuda_bf16.h>
#include <math.h>
#include <stdint.h>

#define M_LIB   200000
#define N_PATCH 676
#define NPAD    768
#define DIM     384
#define IMG     224
#define SIGMA   4.0f
#define KRAD    16

#define NTILES  43              // 128-row tiles per stripe; 37 stripes
#define STRIPE  (128*NTILES)    // 5504
#define NITER   (NTILES*6)      // 258 k-sixth stages
#define STG_BYTES (128*128)     // one stage: 128 rows x 64 k-elems bf16 (128B pitch)
#define SM_P    0               // patch chunk 96 x 768B = 73728
#define SM_L    73728
#define SM_MIN  (SM_L + 2*STG_BYTES)   // 106496
#define SMEM_MAIN (SM_MIN + 96*8)      // 107264

// ---------------- device scratch ----------------
__device__ __align__(16) __nv_bfloat16 g_lib_bf16[(size_t)M_LIB * DIM];
__device__ float g_ln[M_LIB];
__device__ float g_patch_n[N_PATCH * DIM];
__device__ __align__(16) __nv_bfloat16 g_patch_bf16[NPAD * DIM];
__device__ float g_pn[N_PATCH];
__device__ unsigned long long g_minbuf[NPAD];
__device__ float g_minval[N_PATCH];
__device__ int   g_sidx;
__device__ int   g_mstar_idx;
__device__ float g_sstar;
__device__ float g_d2star[M_LIB];
__device__ unsigned long long g_btop[64 * 5];
__device__ int   g_nn[5];
__device__ float g_map_a[IMG * IMG];
__device__ float g_map_b[IMG * IMG];

// ---------------- helpers ----------------
__device__ __forceinline__ unsigned fordu(float f) {
    unsigned u = __float_as_uint(f);
    return (u & 0x80000000u) ? ~u : (u | 0x80000000u);
}
__device__ __forceinline__ float fordu_inv(unsigned e) {
    return __uint_as_float((e & 0x80000000u) ? (e ^ 0x80000000u) : ~e);
}
__device__ __forceinline__ unsigned long long packkey(float v, int idx) {
    return ((unsigned long long)fordu(v) << 32) | (unsigned)idx;
}
__device__ __forceinline__ unsigned long long ullmin2(unsigned long long a, unsigned long long b) {
    return a < b ? a : b;
}
#define INF_F (__int_as_float(0x7f800000))

__device__ __forceinline__ uint32_t smem_u32(const void* p) {
    return (uint32_t)__cvta_generic_to_shared(p);
}

#define LDSM4(r0,r1,r2,r3,addr) \
    asm volatile("ldmatrix.sync.aligned.m8n8.x4.shared.b16 {%0,%1,%2,%3}, [%4];" \
        : "=r"(r0), "=r"(r1), "=r"(r2), "=r"(r3) : "r"(addr))
#define MMA16816(D,a0,a1,a2,a3,b0,b1) \
    asm volatile("mma.sync.aligned.m16n8k16.row.col.f32.bf16.bf16.f32 " \
        "{%0,%1,%2,%3},{%4,%5,%6,%7},{%8,%9},{%0,%1,%2,%3};" \
        : "+f"((D)[0]), "+f"((D)[1]), "+f"((D)[2]), "+f"((D)[3]) \
        : "r"(a0), "r"(a1), "r"(a2), "r"(a3), "r"(b0), "r"(b1))

__device__ __forceinline__ void cp16(uint32_t dst, const void* src, uint32_t nbytes) {
    asm volatile("cp.async.cg.shared.global [%0], [%1], 16, %2;"
                 :: "r"(dst), "l"(src), "r"(nbytes) : "memory");
}
#define CP_COMMIT() asm volatile("cp.async.commit_group;" ::: "memory")
#define CP_WAIT1()  asm volatile("cp.async.wait_group 1;" ::: "memory")

// ---------------- 1. normalize patch (+ minbuf init in padding blocks) ----
__global__ void k_prep_patch(const float* __restrict__ patch) {
    int n = blockIdx.x, t = threadIdx.x;  // 128 thr
    if (n >= N_PATCH) {
        #pragma unroll
        for (int j = 0; j < 3; j++) g_patch_bf16[n * DIM + t + 128 * j] = __float2bfloat16(0.f);
        int idx = (n - N_PATCH) * 128 + t;
        if (idx < NPAD) g_minbuf[idx] = ~0ull;
        return;
    }
    __shared__ float red[128];
    float v[3]; float ss = 0.f;
    #pragma unroll
    for (int j = 0; j < 3; j++) { v[j] = patch[(size_t)n * DIM + t + 128 * j]; ss += v[j] * v[j]; }
    red[t] = ss; __syncthreads();
    for (int s = 64; s > 0; s >>= 1) { if (t < s) red[t] += red[t + s]; __syncthreads(); }
    float denom = fmaxf(sqrtf(red[0]), 1e-12f);
    __syncthreads();
    float pn = 0.f;
    #pragma unroll
    for (int j = 0; j < 3; j++) {
        float x = v[j] / denom; pn += x * x;
        g_patch_n[n * DIM + t + 128 * j] = x;
        g_patch_bf16[n * DIM + t + 128 * j] = __float2bfloat16(x);
    }
    red[t] = pn; __syncthreads();
    for (int s = 64; s > 0; s >>= 1) { if (t < s) red[t] += red[t + s]; __syncthreads(); }
    if (t == 0) g_pn[n] = red[0];
}

// ---------------- 2. lib fp32 -> bf16 + ln ----------------
__global__ void k_prep_lib(const float* __restrict__ lib) {
    int w = threadIdx.x >> 5, lane = threadIdx.x & 31;
    int row = blockIdx.x * 8 + w;
    const float4* src = (const float4*)(lib + (size_t)row * DIM);
    __nv_bfloat162* dst = (__nv_bfloat162*)(g_lib_bf16 + (size_t)row * DIM);
    float ss = 0.f;
    #pragma unroll
    for (int j = 0; j < 3; j++) {
        float4 f = src[lane + 32 * j];
        ss += f.x * f.x + f.y * f.y + f.z * f.z + f.w * f.w;
        dst[2 * (lane + 32 * j)]     = __floats2bfloat162_rn(f.x, f.y);
        dst[2 * (lane + 32 * j) + 1] = __floats2bfloat162_rn(f.z, f.w);
    }
    for (int o = 16; o; o >>= 1) ss += __shfl_xor_sync(0xffffffffu, ss, o);
    if (lane == 0) g_ln[row] = ss;
}

// ---------------- 4. fused bf16 HMMA GEMM + per-patch-row max-dot ----------
// grid 296 = 8 n-chunks x 37 stripes; 256 threads; TWO CTAs per SM.
// CTA tile 128m x 96n, 8 warps as 4 wm x 2 wn, warp tile 32m x 48n.
// Lib streamed as 128-row tiles in 6 k-sixths (128B pitch), 2-stage cp.async.
__global__ void __launch_bounds__(256, 2) k_main() {
    extern __shared__ char sm[];
    const uint32_t smb = smem_u32(sm);
    unsigned long long* sMin = (unsigned long long*)(sm + SM_MIN);
    const int tid = threadIdx.x;
    const int warp = tid >> 5, lane = tid & 31;
    const int nc = blockIdx.x & 7;
    const int mBase = (blockIdx.x >> 3) * STRIPE;

    if (tid < 96) sMin[tid] = ~0ull;

    // --- stage resident patch chunk [96 x 384] bf16, swizzled 768B rows ---
    for (int i = tid; i < 96 * 48; i += 256) {
        int r = i / 48, u = i % 48;
        uint32_t dst = smb + SM_P + r * 768 + (((u ^ (r & 7))) << 4);
        cp16(dst, g_patch_bf16 + (size_t)(nc * 96 + r) * DIM + u * 8, 16);
    }
    // --- prologue: stage0 (grouped with patch), stage1 ---
    const int pu = tid & 7, pr0 = tid >> 3;    // 4 rows per thread
    #pragma unroll
    for (int p = 0; p < 2; p++) {
        #pragma unroll
        for (int j = 0; j < 4; j++) {
            int r = pr0 + 32 * j;
            int g = mBase + r;
            cp16(smb + SM_L + p * STG_BYTES + r * 128 + (((pu ^ (r & 7))) << 4),
                 g_lib_bf16 + (size_t)min(g, M_LIB - 1) * DIM + p * 64 + pu * 8,
                 (g < M_LIB) ? 16u : 0u);
        }
        CP_COMMIT();
    }

    // --- per-thread invariants ---
    const int wm = warp & 3, wn = warp >> 2;      // 4 x 2, warp tile 32m x 48n
    const unsigned hiA = (lane >> 4);
    const unsigned hiB = (lane >> 3) & 1;
    unsigned baseA[2], swA[2];
    #pragma unroll
    for (int mf = 0; mf < 2; mf++) {
        unsigned rA = 32 * wm + 16 * mf + (lane & 15);
        baseA[mf] = rA * 128;
        swA[mf] = rA & 7;
    }
    unsigned pBase[3], swB[3];
    #pragma unroll
    for (int f2 = 0; f2 < 3; f2++) {
        unsigned rB = 48 * wn + 16 * f2 + (lane & 7) + ((lane >> 4) << 3);
        pBase[f2] = smb + SM_P + rB * 768;
        swB[f2] = rB & 7;
    }
    const int g8 = lane >> 2, tig = lane & 3;

    float runV[12]; int runI[12];
    #pragma unroll
    for (int j = 0; j < 12; j++) { runV[j] = -INF_F; runI[j] = 0; }

    float acc[12][4];
    #pragma unroll
    for (int g = 0; g < 12; g++) acc[g][0] = acc[g][1] = acc[g][2] = acc[g][3] = 0.f;

    int s = 0, q = 0, tile = 0;
    for (int i = 0; i < NITER; i++) {
        CP_WAIT1();
        __syncthreads();
        // compute stage i: 4 ksteps, 2 A-frags + 3 B-frags, 12 MMAs each
        const unsigned stgA = smb + SM_L + s * STG_BYTES;
        const unsigned pq = q * 128;
        #pragma unroll
        for (int ks = 0; ks < 4; ks++) {
            unsigned a[2][4];
            unsigned uA = 2 * ks + hiA;
            #pragma unroll
            for (int mf = 0; mf < 2; mf++)
                LDSM4(a[mf][0], a[mf][1], a[mf][2], a[mf][3],
                      stgA + baseA[mf] + (((uA ^ swA[mf])) << 4));
            unsigned uB = hiB + 2 * ks;
            #pragma unroll
            for (int f2 = 0; f2 < 3; f2++) {
                unsigned r0, r1, r2, r3;
                LDSM4(r0, r1, r2, r3, pBase[f2] + pq + (((uB ^ swB[f2])) << 4));
                #pragma unroll
                for (int mf = 0; mf < 2; mf++) {
                    MMA16816(acc[(mf * 3 + f2) * 2],     a[mf][0], a[mf][1], a[mf][2], a[mf][3], r0, r1);
                    MMA16816(acc[(mf * 3 + f2) * 2 + 1], a[mf][0], a[mf][1], a[mf][2], a[mf][3], r2, r3);
                }
            }
        }
        __syncthreads();
        // prefetch stage i+2 into the buffer just consumed
        {
            int nx = i + 2;
            if (nx < NITER) {
                int tN = nx / 6, qN = nx - tN * 6;
                int mN = mBase + tN * 128;
                const __nv_bfloat16* srcb = g_lib_bf16 + (size_t)qN * 64;
                #pragma unroll
                for (int j = 0; j < 4; j++) {
                    int r = pr0 + 32 * j;
                    int g = mN + r;
                    cp16(smb + SM_L + s * STG_BYTES + r * 128 + (((pu ^ (r & 7))) << 4),
                         srcb + (size_t)min(g, M_LIB - 1) * DIM + pu * 8,
                         (g < M_LIB) ? 16u : 0u);
                }
            }
            CP_COMMIT();
        }
        s ^= 1;
        q++;
        if (q == 6) {
            q = 0;
            // tile epilogue: fold 128-row tile into per-column running max dot
            int mt = mBase + tile * 128;
            #pragma unroll
            for (int g = 0; g < 12; g++) {
                int mf = g / 6;
                int mlo = mt + 32 * wm + 16 * mf + g8, mhi = mlo + 8;
                bool okLo = mlo < M_LIB, okHi = mhi < M_LIB;
                int jj = (g % 6) * 2;
                #pragma unroll
                for (int c = 0; c < 2; c++) {
                    float vlo = acc[g][c], vhi = acc[g][2 + c];
                    if (okLo && vlo > runV[jj + c]) { runV[jj + c] = vlo; runI[jj + c] = mlo; }
                    if (okHi && vhi > runV[jj + c]) { runV[jj + c] = vhi; runI[jj + c] = mhi; }
                }
                acc[g][0] = acc[g][1] = acc[g][2] = acc[g][3] = 0.f;
            }
            tile++;
        }
    }

    // reduce over the 8 lanes sharing each column
    #pragma unroll
    for (int off = 4; off < 32; off <<= 1) {
        #pragma unroll
        for (int j = 0; j < 12; j++) {
            float ov = __shfl_xor_sync(0xffffffffu, runV[j], off);
            int   oi = __shfl_xor_sync(0xffffffffu, runI[j], off);
            if (ov > runV[j]) { runV[j] = ov; runI[j] = oi; }
        }
    }
    if (g8 == 0) {
        #pragma unroll
        for (int jj = 0; jj < 12; jj++) {
            int f2 = jj >> 2, nh = (jj >> 1) & 1, c = jj & 1;
            int col = 48 * wn + 16 * f2 + 8 * nh + 2 * tig + c;
            atomicMin(&sMin[col], packkey(-runV[jj], runI[jj]));
        }
    }
    __syncthreads();
    if (tid < 96) atomicMin(&g_minbuf[nc * 96 + tid], sMin[tid]);
}

// ---------------- 5. min_val per n + argmax over n ----------------
__global__ void k_nmin() {
    int t = threadIdx.x;  // 1024
    __shared__ float rv[1024]; __shared__ int ri[1024];
    float mv = -INF_F; int idx = 0;
    if (t < N_PATCH) {
        unsigned long long key = g_minbuf[t];
        int mi = (int)(key & 0xffffffffu);
        float v = fordu_inv((unsigned)(key >> 32));   // = -max_dot
        float d2 = g_pn[t] + g_ln[mi] + 2.f * v;
        mv = sqrtf(fmaxf(d2, 0.f));
        g_minval[t] = mv; idx = t;
    }
    rv[t] = mv; ri[t] = idx; __syncthreads();
    for (int s = 512; s > 0; s >>= 1) {
        if (t < s && rv[t + s] > rv[t]) { rv[t] = rv[t + s]; ri[t] = ri[t + s]; }
        __syncthreads();
    }
    if (t == 0) {
        g_sidx = ri[0]; g_sstar = rv[0];
        g_mstar_idx = (int)(g_minbuf[ri[0]] & 0xffffffffu);
    }
}

// ---------------- 6. d*^2 (shifted) over all lib rows ----------------
__global__ void k_pass2() {
    int w = threadIdx.x >> 5, lane = threadIdx.x & 31;
    int row = blockIdx.x * 8 + w;
    int msi = g_mstar_idx;
    const unsigned* a = (const unsigned*)(g_lib_bf16 + (size_t)row * DIM);
    const unsigned* b = (const unsigned*)(g_lib_bf16 + (size_t)msi * DIM);
    float dot = 0.f;
    #pragma unroll
    for (int j = 0; j < 6; j++) {
        unsigned ua = a[lane + 32 * j], ub = b[lane + 32 * j];
        float2 fa = __bfloat1622float2(*(__nv_bfloat162*)&ua);
        float2 fb = __bfloat1622float2(*(__nv_bfloat162*)&ub);
        dot = fmaf(fa.x, fb.x, dot); dot = fmaf(fa.y, fb.y, dot);
    }
    for (int o = 16; o; o >>= 1) dot += __shfl_xor_sync(0xffffffffu, dot, o);
    if (lane == 0) g_d2star[row] = g_ln[row] - 2.f * dot;
}

// ---------------- 7. top-5 smallest, block stage ----------------
__global__ void k_topscan() {
    unsigned long long best[5];
    #pragma unroll
    for (int r = 0; r < 5; r++) best[r] = ~0ull;
    for (int m = blockIdx.x * 256 + threadIdx.x; m < M_LIB; m += 64 * 256) {
        unsigned long long key = packkey(g_d2star[m], m);
        if (key < best[4]) {
            best[4] = key;
            #pragma unroll
            for (int r = 4; r > 0; r--)
                if (best[r] < best[r - 1]) { unsigned long long tm = best[r]; best[r] = best[r - 1]; best[r - 1] = tm; }
        }
    }
    __shared__ unsigned long long sb[5 * 256], red[256], winner;
    int t = threadIdx.x;
    #pragma unroll
    for (int r = 0; r < 5; r++) sb[r * 256 + t] = best[r];
    __syncthreads();
    for (int round = 0; round < 5; round++) {
        unsigned long long mn = ~0ull;
        #pragma unroll
        for (int r = 0; r < 5; r++) mn = ullmin2(mn, sb[r * 256 + t]);
        red[t] = mn; __syncthreads();
        for (int s = 128; s > 0; s >>= 1) { if (t < s) red[t] = ullmin2(red[t], red[t + s]); __syncthreads(); }
        if (t == 0) { winner = red[0]; g_btop[blockIdx.x * 5 + round] = red[0]; }
        __syncthreads();
        unsigned long long wv = winner;
        #pragma unroll
        for (int r = 0; r < 5; r++) if (sb[r * 256 + t] == wv) sb[r * 256 + t] = ~0ull;
        __syncthreads();
    }
}

// ---------------- 8. top-5 final merge ----------------
__global__ void k_topfinal() {
    __shared__ unsigned long long sb[320], red[256], winner;
    int t = threadIdx.x;  // 256
    sb[t] = g_btop[t];
    if (t < 64) sb[256 + t] = g_btop[256 + t];
    __syncthreads();
    for (int round = 0; round < 5; round++) {
        unsigned long long mn = sb[t];
        if (t < 64) mn = ullmin2(mn, sb[256 + t]);
        red[t] = mn; __syncthreads();
        for (int s = 128; s > 0; s >>= 1) { if (t < s) red[t] = ullmin2(red[t], red[t + s]); __syncthreads(); }
        if (t == 0) { winner = red[0]; g_nn[round] = (int)(red[0] & 0xffffffffu); }
        __syncthreads();
        unsigned long long wv = winner;
        if (sb[t] == wv) sb[t] = ~0ull;
        if (t < 64 && sb[256 + t] == wv) sb[256 + t] = ~0ull;
        __syncthreads();
    }
}

// ---------------- 9. scalar s ----------------
__global__ void k_scalar(const float* __restrict__ lib, float* __restrict__ out, int write_s) {
    __shared__ float red[6][128];
    int t = threadIdx.x;  // 128
    int sidx = g_sidx, msi = g_mstar_idx;
    int nn[5];
    #pragma unroll
    for (int i = 0; i < 5; i++) nn[i] = g_nn[i];
    float ss[6] = {0.f, 0.f, 0.f, 0.f, 0.f, 0.f};
    #pragma unroll
    for (int j = 0; j < 3; j++) {
        int col = t + 128 * j;
        float p = g_patch_n[sidx * DIM + col];
        float d0 = p - lib[(size_t)msi * DIM + col];
        ss[0] += d0 * d0;
        #pragma unroll
        for (int i = 0; i < 5; i++) {
            float d = p - lib[(size_t)nn[i] * DIM + col];
            ss[1 + i] += d * d;
        }
    }
    #pragma unroll
    for (int q = 0; q < 6; q++) red[q][t] = ss[q];
    __syncthreads();
    for (int s = 64; s > 0; s >>= 1) {
        if (t < s) {
            #pragma unroll
            for (int q = 0; q < 6; q++) red[q][t] += red[q][t + s];
        }
        __syncthreads();
    }
    if (t == 0 && write_s) {
        float num = expf(sqrtf(red[0][0]));
        float den = 0.f;
        #pragma unroll
        for (int i = 0; i < 5; i++) den += expf(sqrtf(red[1 + i][0]));
        out[0] = (1.f - num / den) * g_sstar;
    }
}

// ---------------- 10. bilinear 26 -> 224 ----------------
__global__ void k_upsample() {
    int x = blockIdx.x * 32 + threadIdx.x;
    int y = blockIdx.y * 8 + threadIdx.y;
    if (x >= IMG || y >= IMG) return;
    const float scale = 26.f / 224.f;
    float sx = (x + 0.5f) * scale - 0.5f;
    float sy = (y + 0.5f) * scale - 0.5f;
    int x0 = (int)floorf(sx), y0 = (int)floorf(sy);
    float fx = sx - x0, fy = sy - y0;
    int x0c = min(max(x0, 0), 25), x1c = min(max(x0 + 1, 0), 25);
    int y0c = min(max(y0, 0), 25), y1c = min(max(y0 + 1, 0), 25);
    float v00 = g_minval[y0c * 26 + x0c], v01 = g_minval[y0c * 26 + x1c];
    float v10 = g_minval[y1c * 26 + x0c], v11 = g_minval[y1c * 26 + x1c];
    float top = v00 + fx * (v01 - v00), bot = v10 + fx * (v11 - v10);
    g_map_a[y * IMG + x] = top + fy * (bot - top);
}

__device__ __forceinline__ int reflect_idx(int j) {
    if (j < 0) j = -j;
    if (j > IMG - 1) j = 2 * (IMG - 1) - j;
    return j;
}
__device__ __forceinline__ void blur_weights(float* w) {
    float s = 0.f;
    #pragma unroll
    for (int i = 0; i < 33; i++) {
        float xx = (float)(i - KRAD) / SIGMA;
        w[i] = expf(-0.5f * xx * xx); s += w[i];
    }
    float inv = 1.f / s;
    #pragma unroll
    for (int i = 0; i < 33; i++) w[i] *= inv;
}
__global__ void k_blur_v() {
    int x = blockIdx.x * 32 + threadIdx.x;
    int y = blockIdx.y * 8 + threadIdx.y;
    if (x >= IMG || y >= IMG) return;
    float w[33]; blur_weights(w);
    float acc = 0.f;
    #pragma unroll
    for (int i = 0; i < 33; i++) acc += w[i] * g_map_a[reflect_idx(y + i - KRAD) * IMG + x];
    g_map_b[y * IMG + x] = acc;
}
__global__ void k_blur_h(float* __restrict__ out) {
    int x = blockIdx.x * 32 + threadIdx.x;
    int y = blockIdx.y * 8 + threadIdx.y;
    if (x >= IMG || y >= IMG) return;
    float w[33]; blur_weights(w);
    float acc = 0.f;
    #pragma unroll
    for (int i = 0; i < 33; i++) acc += w[i] * g_map_b[y * IMG + reflect_idx(x + i - KRAD)];
    out[y * IMG + x] = acc;
}

extern "C" void kernel_launch(void* const* d_in, const int* in_sizes, int n_in,
                              void* d_out, int out_size) {
    const float* patch = (const float*)d_in[0];
    const float* lib   = (const float*)d_in[1];
    if (n_in >= 2 && in_sizes[0] != N_PATCH * DIM) {
        patch = (const float*)d_in[1]; lib = (const float*)d_in[0];
    }
    float* out = (float*)d_out;
    int ofs = out_size - IMG * IMG;
    if (ofs < 0) ofs = 0;

    static int smem_set = 0;
    if (!smem_set) {
        cudaFuncSetAttribute(k_main, cudaFuncAttributeMaxDynamicSharedMemorySize, SMEM_MAIN);
        smem_set = 1;
    }

    k_prep_patch<<<NPAD, 128>>>(patch);
    k_prep_lib<<<M_LIB / 8, 256>>>(lib);
    k_main<<<296, 256, SMEM_MAIN>>>();
    k_nmin<<<1, 1024>>>();
    k_pass2<<<M_LIB / 8, 256>>>();
    k_topscan<<<64, 256>>>();
    k_topfinal<<<1, 256>>>();
    k_scalar<<<1, 128>>>(lib, out, ofs > 0 ? 1 : 0);
    dim3 blk(32, 8), grd(7, 28);
    k_upsample<<<grd, blk>>>();
    k_blur_v<<<grd, blk>>>();
    k_blur_h<<<grd, blk>>>(out + ofs);
}

// round 15
// speedup vs baseline: 1.0923x; 1.0361x over previous
#include <cuda_runtime.h>
#include <cuda_bf16.h>
#include <math.h>
#include <stdint.h>

#define M_LIB   200000
#define M_PAD   203648          // 37 * 5504, zero-padded tail (bss)
#define N_PATCH 676
#define NPAD    768
#define DIM     384
#define IMG     224
#define SIGMA   4.0f
#define KRAD    16

#define NTILES  43              // 128-row tiles per stripe; 37 stripes
#define STRIPE  (128*NTILES)    // 5504
#define NITER   (NTILES*6)      // 258 k-sixth stages
#define STG_BYTES (128*128)     // one stage: 128 rows x 64 k-elems bf16 (128B pitch)
#define SM_P    0               // patch chunk 96 x 768B = 73728
#define SM_L    73728
#define SM_MIN  (SM_L + 2*STG_BYTES)   // 106496
#define SMEM_MAIN (SM_MIN + 96*8)      // 107264

// ---------------- device scratch ----------------
__device__ __align__(16) __nv_bfloat16 g_lib_bf16[(size_t)M_PAD * DIM];  // pad rows stay 0
__device__ float g_patch_n[N_PATCH * DIM];
__device__ __align__(16) __nv_bfloat16 g_patch_bf16[NPAD * DIM];
__device__ float g_pn[N_PATCH];
__device__ unsigned long long g_minbuf[NPAD];
__device__ float g_minval[N_PATCH];
__device__ int   g_sidx;
__device__ int   g_mstar_idx;
__device__ float g_sstar;
__device__ float g_d2star[M_LIB];
__device__ unsigned long long g_btop[64 * 5];
__device__ int   g_nn[5];

// ---------------- helpers ----------------
__device__ __forceinline__ unsigned fordu(float f) {
    unsigned u = __float_as_uint(f);
    return (u & 0x80000000u) ? ~u : (u | 0x80000000u);
}
__device__ __forceinline__ float fordu_inv(unsigned e) {
    return __uint_as_float((e & 0x80000000u) ? (e ^ 0x80000000u) : ~e);
}
__device__ __forceinline__ unsigned long long packkey(float v, int idx) {
    return ((unsigned long long)fordu(v) << 32) | (unsigned)idx;
}
__device__ __forceinline__ unsigned long long ullmin2(unsigned long long a, unsigned long long b) {
    return a < b ? a : b;
}
#define INF_F (__int_as_float(0x7f800000))

__device__ __forceinline__ uint32_t smem_u32(const void* p) {
    return (uint32_t)__cvta_generic_to_shared(p);
}

#define LDSM4(r0,r1,r2,r3,addr) \
    asm volatile("ldmatrix.sync.aligned.m8n8.x4.shared.b16 {%0,%1,%2,%3}, [%4];" \
        : "=r"(r0), "=r"(r1), "=r"(r2), "=r"(r3) : "r"(addr))
#define MMA16816(D,a0,a1,a2,a3,b0,b1) \
    asm volatile("mma.sync.aligned.m16n8k16.row.col.f32.bf16.bf16.f32 " \
        "{%0,%1,%2,%3},{%4,%5,%6,%7},{%8,%9},{%0,%1,%2,%3};" \
        : "+f"((D)[0]), "+f"((D)[1]), "+f"((D)[2]), "+f"((D)[3]) \
        : "r"(a0), "r"(a1), "r"(a2), "r"(a3), "r"(b0), "r"(b1))

__device__ __forceinline__ void cp16(uint32_t dst, const void* src) {
    asm volatile("cp.async.cg.shared.global [%0], [%1], 16;"
                 :: "r"(dst), "l"(src) : "memory");
}
#define CP_COMMIT() asm volatile("cp.async.commit_group;" ::: "memory")
#define CP_WAIT1()  asm volatile("cp.async.wait_group 1;" ::: "memory")

// ---------------- 1. normalize patch (+ minbuf init in padding blocks) ----
__global__ void k_prep_patch(const float* __restrict__ patch) {
    int n = blockIdx.x, t = threadIdx.x;  // 128 thr
    if (n >= N_PATCH) {
        #pragma unroll
        for (int j = 0; j < 3; j++) g_patch_bf16[n * DIM + t + 128 * j] = __float2bfloat16(0.f);
        int idx = (n - N_PATCH) * 128 + t;
        if (idx < NPAD) g_minbuf[idx] = ~0ull;
        return;
    }
    __shared__ float red[128];
    float v[3]; float ss = 0.f;
    #pragma unroll
    for (int j = 0; j < 3; j++) { v[j] = patch[(size_t)n * DIM + t + 128 * j]; ss += v[j] * v[j]; }
    red[t] = ss; __syncthreads();
    for (int s = 64; s > 0; s >>= 1) { if (t < s) red[t] += red[t + s]; __syncthreads(); }
    float denom = fmaxf(sqrtf(red[0]), 1e-12f);
    __syncthreads();
    float pn = 0.f;
    #pragma unroll
    for (int j = 0; j < 3; j++) {
        float x = v[j] / denom; pn += x * x;
        g_patch_n[n * DIM + t + 128 * j] = x;
        g_patch_bf16[n * DIM + t + 128 * j] = __float2bfloat16(x);
    }
    red[t] = pn; __syncthreads();
    for (int s = 64; s > 0; s >>= 1) { if (t < s) red[t] += red[t + s]; __syncthreads(); }
    if (t == 0) g_pn[n] = red[0];
}

// ---------------- 2. lib fp32 -> bf16 (pure convert; lib is pre-normalized) -
__global__ void k_prep_lib(const float* __restrict__ lib) {
    int w = threadIdx.x >> 5, lane = threadIdx.x & 31;
    int row = blockIdx.x * 8 + w;
    const float4* src = (const float4*)(lib + (size_t)row * DIM);
    __nv_bfloat162* dst = (__nv_bfloat162*)(g_lib_bf16 + (size_t)row * DIM);
    #pragma unroll
    for (int j = 0; j < 3; j++) {
        float4 f = src[lane + 32 * j];
        dst[2 * (lane + 32 * j)]     = __floats2bfloat162_rn(f.x, f.y);
        dst[2 * (lane + 32 * j) + 1] = __floats2bfloat162_rn(f.z, f.w);
    }
}

// ---------------- 4. fused bf16 HMMA GEMM + per-patch-row max-dot ----------
// grid 296 = 8 n-chunks x 37 stripes; 256 threads; TWO CTAs per SM.
// CTA tile 128m x 96n, 8 warps as 4 wm x 2 wn, warp tile 32m x 48n.
// Lib zero-padded to M_PAD: no bounds checks anywhere in the hot loop.
__global__ void __launch_bounds__(256, 2) k_main() {
    extern __shared__ char sm[];
    const uint32_t smb = smem_u32(sm);
    unsigned long long* sMin = (unsigned long long*)(sm + SM_MIN);
    const int tid = threadIdx.x;
    const int warp = tid >> 5, lane = tid & 31;
    const int nc = blockIdx.x & 7;
    const int mBase = (blockIdx.x >> 3) * STRIPE;

    if (tid < 96) sMin[tid] = ~0ull;

    // --- stage resident patch chunk [96 x 384] bf16, swizzled 768B rows ---
    for (int i = tid; i < 96 * 48; i += 256) {
        int r = i / 48, u = i % 48;
        uint32_t dst = smb + SM_P + r * 768 + (((u ^ (r & 7))) << 4);
        cp16(dst, g_patch_bf16 + (size_t)(nc * 96 + r) * DIM + u * 8);
    }
    // --- prologue: stage0 (grouped with patch), stage1 ---
    const int pu = tid & 7, pr0 = tid >> 3;    // 4 rows per thread
    #pragma unroll
    for (int p = 0; p < 2; p++) {
        #pragma unroll
        for (int j = 0; j < 4; j++) {
            int r = pr0 + 32 * j;
            cp16(smb + SM_L + p * STG_BYTES + r * 128 + (((pu ^ (r & 7))) << 4),
                 g_lib_bf16 + (size_t)(mBase + r) * DIM + p * 64 + pu * 8);
        }
        CP_COMMIT();
    }

    // --- per-thread invariants ---
    const int wm = warp & 3, wn = warp >> 2;      // 4 x 2, warp tile 32m x 48n
    const unsigned hiA = (lane >> 4);
    const unsigned hiB = (lane >> 3) & 1;
    unsigned baseA[2], swA[2];
    #pragma unroll
    for (int mf = 0; mf < 2; mf++) {
        unsigned rA = 32 * wm + 16 * mf + (lane & 15);
        baseA[mf] = rA * 128;
        swA[mf] = rA & 7;
    }
    unsigned pBase[3], swB[3];
    #pragma unroll
    for (int f2 = 0; f2 < 3; f2++) {
        unsigned rB = 48 * wn + 16 * f2 + (lane & 7) + ((lane >> 4) << 3);
        pBase[f2] = smb + SM_P + rB * 768;
        swB[f2] = rB & 7;
    }
    const int g8 = lane >> 2, tig = lane & 3;

    float runV[12]; int runI[12];
    #pragma unroll
    for (int j = 0; j < 12; j++) { runV[j] = -INF_F; runI[j] = 0; }

    float acc[12][4];
    #pragma unroll
    for (int g = 0; g < 12; g++) acc[g][0] = acc[g][1] = acc[g][2] = acc[g][3] = 0.f;

    int s = 0, q = 0, tile = 0;
    for (int i = 0; i < NITER; i++) {
        CP_WAIT1();
        __syncthreads();
        // compute stage i: 4 ksteps, 2 A-frags + 3 B-frags, 12 MMAs each
        const unsigned stgA = smb + SM_L + s * STG_BYTES;
        const unsigned pq = q * 128;
        #pragma unroll
        for (int ks = 0; ks < 4; ks++) {
            unsigned a[2][4];
            unsigned uA = 2 * ks + hiA;
            #pragma unroll
            for (int mf = 0; mf < 2; mf++)
                LDSM4(a[mf][0], a[mf][1], a[mf][2], a[mf][3],
                      stgA + baseA[mf] + (((uA ^ swA[mf])) << 4));
            unsigned uB = hiB + 2 * ks;
            #pragma unroll
            for (int f2 = 0; f2 < 3; f2++) {
                unsigned r0, r1, r2, r3;
                LDSM4(r0, r1, r2, r3, pBase[f2] + pq + (((uB ^ swB[f2])) << 4));
                #pragma unroll
                for (int mf = 0; mf < 2; mf++) {
                    MMA16816(acc[(mf * 3 + f2) * 2],     a[mf][0], a[mf][1], a[mf][2], a[mf][3], r0, r1);
                    MMA16816(acc[(mf * 3 + f2) * 2 + 1], a[mf][0], a[mf][1], a[mf][2], a[mf][3], r2, r3);
                }
            }
        }
        __syncthreads();
        // prefetch stage i+2 into the buffer just consumed
        {
            int nx = i + 2;
            if (nx < NITER) {
                int tN = nx / 6, qN = nx - tN * 6;
                const __nv_bfloat16* srcb = g_lib_bf16 + (size_t)qN * 64
                                          + (size_t)(mBase + tN * 128) * DIM + pu * 8;
                #pragma unroll
                for (int j = 0; j < 4; j++) {
                    int r = pr0 + 32 * j;
                    cp16(smb + SM_L + s * STG_BYTES + r * 128 + (((pu ^ (r & 7))) << 4),
                         srcb + (size_t)r * DIM);
                }
            }
            CP_COMMIT();
        }
        s ^= 1;
        q++;
        if (q == 6) {
            q = 0;
            // tile epilogue: fold 128-row tile into per-column running max dot
            int mt = mBase + tile * 128;
            #pragma unroll
            for (int g = 0; g < 12; g++) {
                int mf = g / 6;
                int mlo = mt + 32 * wm + 16 * mf + g8, mhi = mlo + 8;
                int jj = (g % 6) * 2;
                #pragma unroll
                for (int c = 0; c < 2; c++) {
                    float vlo = acc[g][c], vhi = acc[g][2 + c];
                    if (vlo > runV[jj + c]) { runV[jj + c] = vlo; runI[jj + c] = mlo; }
                    if (vhi > runV[jj + c]) { runV[jj + c] = vhi; runI[jj + c] = mhi; }
                }
                acc[g][0] = acc[g][1] = acc[g][2] = acc[g][3] = 0.f;
            }
            tile++;
        }
    }

    // reduce over the 8 lanes sharing each column
    #pragma unroll
    for (int off = 4; off < 32; off <<= 1) {
        #pragma unroll
        for (int j = 0; j < 12; j++) {
            float ov = __shfl_xor_sync(0xffffffffu, runV[j], off);
            int   oi = __shfl_xor_sync(0xffffffffu, runI[j], off);
            if (ov > runV[j]) { runV[j] = ov; runI[j] = oi; }
        }
    }
    if (g8 == 0) {
        #pragma unroll
        for (int jj = 0; jj < 12; jj++) {
            int f2 = jj >> 2, nh = (jj >> 1) & 1, c = jj & 1;
            int col = 48 * wn + 16 * f2 + 8 * nh + 2 * tig + c;
            atomicMin(&sMin[col], packkey(-runV[jj], runI[jj]));
        }
    }
    __syncthreads();
    if (tid < 96) atomicMin(&g_minbuf[nc * 96 + tid], sMin[tid]);
}

// ---------------- 5. min_val per n + argmax over n (ln == 1) --------------
__global__ void k_nmin() {
    int t = threadIdx.x;  // 704 = 22 warps
    int lane = t & 31, w = t >> 5;
    __shared__ float sv[22]; __shared__ int si[22];
    float mv = -INF_F; int idx = 0;
    if (t < N_PATCH) {
        unsigned long long key = g_minbuf[t];
        float v = fordu_inv((unsigned)(key >> 32));   // = -max_dot
        float d2 = g_pn[t] + 1.0f + 2.f * v;
        mv = sqrtf(fmaxf(d2, 0.f));
        g_minval[t] = mv; idx = t;
    }
    #pragma unroll
    for (int o = 16; o; o >>= 1) {
        float ov = __shfl_xor_sync(0xffffffffu, mv, o);
        int oi = __shfl_xor_sync(0xffffffffu, idx, o);
        if (ov > mv) { mv = ov; idx = oi; }
    }
    if (lane == 0) { sv[w] = mv; si[w] = idx; }
    __syncthreads();
    if (t < 32) {
        mv = (t < 22) ? sv[t] : -INF_F;
        idx = (t < 22) ? si[t] : 0;
        #pragma unroll
        for (int o = 16; o; o >>= 1) {
            float ov = __shfl_xor_sync(0xffffffffu, mv, o);
            int oi = __shfl_xor_sync(0xffffffffu, idx, o);
            if (ov > mv) { mv = ov; idx = oi; }
        }
        if (t == 0) {
            g_sidx = idx; g_sstar = mv;
            g_mstar_idx = (int)(g_minbuf[idx] & 0xffffffffu);
        }
    }
}

// ---------------- 6. -dot of every lib row vs m_star (order-equivalent) ---
__global__ void k_pass2() {
    int w = threadIdx.x >> 5, lane = threadIdx.x & 31;
    int row = blockIdx.x * 8 + w;
    int msi = g_mstar_idx;
    const unsigned* a = (const unsigned*)(g_lib_bf16 + (size_t)row * DIM);
    const unsigned* b = (const unsigned*)(g_lib_bf16 + (size_t)msi * DIM);
    float dot = 0.f;
    #pragma unroll
    for (int j = 0; j < 6; j++) {
        unsigned ua = a[lane + 32 * j], ub = b[lane + 32 * j];
        float2 fa = __bfloat1622float2(*(__nv_bfloat162*)&ua);
        float2 fb = __bfloat1622float2(*(__nv_bfloat162*)&ub);
        dot = fmaf(fa.x, fb.x, dot); dot = fmaf(fa.y, fb.y, dot);
    }
    for (int o = 16; o; o >>= 1) dot += __shfl_xor_sync(0xffffffffu, dot, o);
    if (lane == 0) g_d2star[row] = -dot;
}

// ---------------- 7. top-5 smallest, block stage ----------------
__global__ void k_topscan() {
    unsigned long long best[5];
    #pragma unroll
    for (int r = 0; r < 5; r++) best[r] = ~0ull;
    for (int m = blockIdx.x * 256 + threadIdx.x; m < M_LIB; m += 64 * 256) {
        unsigned long long key = packkey(g_d2star[m], m);
        if (key < best[4]) {
            best[4] = key;
            #pragma unroll
            for (int r = 4; r > 0; r--)
                if (best[r] < best[r - 1]) { unsigned long long tm = best[r]; best[r] = best[r - 1]; best[r - 1] = tm; }
        }
    }
    __shared__ unsigned long long sb[5 * 256], red[256], winner;
    int t = threadIdx.x;
    #pragma unroll
    for (int r = 0; r < 5; r++) sb[r * 256 + t] = best[r];
    __syncthreads();
    for (int round = 0; round < 5; round++) {
        unsigned long long mn = ~0ull;
        #pragma unroll
        for (int r = 0; r < 5; r++) mn = ullmin2(mn, sb[r * 256 + t]);
        red[t] = mn; __syncthreads();
        for (int s = 128; s > 0; s >>= 1) { if (t < s) red[t] = ullmin2(red[t], red[t + s]); __syncthreads(); }
        if (t == 0) { winner = red[0]; g_btop[blockIdx.x * 5 + round] = red[0]; }
        __syncthreads();
        unsigned long long wv = winner;
        #pragma unroll
        for (int r = 0; r < 5; r++) if (sb[r * 256 + t] == wv) sb[r * 256 + t] = ~0ull;
        __syncthreads();
    }
}

// ---------------- 8. top-5 final merge ----------------
__global__ void k_topfinal() {
    __shared__ unsigned long long sb[320], red[256], winner;
    int t = threadIdx.x;  // 256
    sb[t] = g_btop[t];
    if (t < 64) sb[256 + t] = g_btop[256 + t];
    __syncthreads();
    for (int round = 0; round < 5; round++) {
        unsigned long long mn = sb[t];
        if (t < 64) mn = ullmin2(mn, sb[256 + t]);
        red[t] = mn; __syncthreads();
        for (int s = 128; s > 0; s >>= 1) { if (t < s) red[t] = ullmin2(red[t], red[t + s]); __syncthreads(); }
        if (t == 0) { winner = red[0]; g_nn[round] = (int)(red[0] & 0xffffffffu); }
        __syncthreads();
        unsigned long long wv = winner;
        if (sb[t] == wv) sb[t] = ~0ull;
        if (t < 64 && sb[256 + t] == wv) sb[256 + t] = ~0ull;
        __syncthreads();
    }
}

// ---------------- 9. scalar s ----------------
__global__ void k_scalar(const float* __restrict__ lib, float* __restrict__ out, int write_s) {
    __shared__ float red[6][128];
    int t = threadIdx.x;  // 128
    int sidx = g_sidx, msi = g_mstar_idx;
    int nn[5];
    #pragma unroll
    for (int i = 0; i < 5; i++) nn[i] = g_nn[i];
    float ss[6] = {0.f, 0.f, 0.f, 0.f, 0.f, 0.f};
    #pragma unroll
    for (int j = 0; j < 3; j++) {
        int col = t + 128 * j;
        float p = g_patch_n[sidx * DIM + col];
        float d0 = p - lib[(size_t)msi * DIM + col];
        ss[0] += d0 * d0;
        #pragma unroll
        for (int i = 0; i < 5; i++) {
            float d = p - lib[(size_t)nn[i] * DIM + col];
            ss[1 + i] += d * d;
        }
    }
    #pragma unroll
    for (int q = 0; q < 6; q++) red[q][t] = ss[q];
    __syncthreads();
    for (int s = 64; s > 0; s >>= 1) {
        if (t < s) {
            #pragma unroll
            for (int q = 0; q < 6; q++) red[q][t] += red[q][t + s];
        }
        __syncthreads();
    }
    if (t == 0 && write_s) {
        float num = expf(sqrtf(red[0][0]));
        float den = 0.f;
        #pragma unroll
        for (int i = 0; i < 5; i++) den += expf(sqrtf(red[1 + i][0]));
        out[0] = (1.f - num / den) * g_sstar;
    }
}

// ---------------- 10. fused bilinear 26->224 + separable 33-tap blur ------
__device__ __forceinline__ int reflect_idx(int j) {
    if (j < 0) j = -j;
    if (j > IMG - 1) j = 2 * (IMG - 1) - j;
    return j;
}
__device__ __forceinline__ float upsample_val(int y, int x) {
    const float scale = 26.f / 224.f;
    float sx = (x + 0.5f) * scale - 0.5f;
    float sy = (y + 0.5f) * scale - 0.5f;
    int x0 = (int)floorf(sx), y0 = (int)floorf(sy);
    float fx = sx - x0, fy = sy - y0;
    int x0c = min(max(x0, 0), 25), x1c = min(max(x0 + 1, 0), 25);
    int y0c = min(max(y0, 0), 25), y1c = min(max(y0 + 1, 0), 25);
    float v00 = g_minval[y0c * 26 + x0c], v01 = g_minval[y0c * 26 + x1c];
    float v10 = g_minval[y1c * 26 + x0c], v11 = g_minval[y1c * 26 + x1c];
    float top = v00 + fx * (v01 - v00), bot = v10 + fx * (v11 - v10);
    return top + fy * (bot - top);
}
__global__ void k_map(float* __restrict__ out) {
    __shared__ float band[40][IMG];
    __shared__ float bv[8][IMG];
    int b = blockIdx.x, t = threadIdx.x;  // 28 blocks x 256 thr
    int y0 = b * 8;
    float w[33];
    {
        float s = 0.f;
        #pragma unroll
        for (int i = 0; i < 33; i++) {
            float xx = (float)(i - KRAD) / SIGMA;
            w[i] = expf(-0.5f * xx * xx); s += w[i];
        }
        float inv = 1.f / s;
        #pragma unroll
        for (int i = 0; i < 33; i++) w[i] *= inv;
    }
    for (int i = t; i < 40 * IMG; i += 256) {
        int k = i / IMG, x = i % IMG;
        band[k][x] = upsample_val(reflect_idx(y0 - KRAD + k), x);
    }
    __syncthreads();
    for (int i = t; i < 8 * IMG; i += 256) {
        int yy = i / IMG, x = i % IMG;
        float acc = 0.f;
        #pragma unroll
        for (int j = 0; j < 33; j++) acc += w[j] * band[yy + j][x];
        bv[yy][x] = acc;
    }
    __syncthreads();
    for (int i = t; i < 8 * IMG; i += 256) {
        int yy = i / IMG, x = i % IMG;
        float acc = 0.f;
        #pragma unroll
        for (int j = 0; j < 33; j++) acc += w[j] * bv[yy][reflect_idx(x + j - KRAD)];
        out[(y0 + yy) * IMG + x] = acc;
    }
}

extern "C" void kernel_launch(void* const* d_in, const int* in_sizes, int n_in,
                              void* d_out, int out_size) {
    const float* patch = (const float*)d_in[0];
    const float* lib   = (const float*)d_in[1];
    if (n_in >= 2 && in_sizes[0] != N_PATCH * DIM) {
        patch = (const float*)d_in[1]; lib = (const float*)d_in[0];
    }
    float* out = (float*)d_out;
    int ofs = out_size - IMG * IMG;
    if (ofs < 0) ofs = 0;

    static int smem_set = 0;
    if (!smem_set) {
        cudaFuncSetAttribute(k_main, cudaFuncAttributeMaxDynamicSharedMemorySize, SMEM_MAIN);
        smem_set = 1;
    }

    k_prep_patch<<<NPAD, 128>>>(patch);
    k_prep_lib<<<M_LIB / 8, 256>>>(lib);
    k_main<<<296, 256, SMEM_MAIN>>>();
    k_nmin<<<1, 704>>>();
    k_pass2<<<M_LIB / 8, 256>>>();
    k_topscan<<<64, 256>>>();
    k_topfinal<<<1, 256>>>();
    k_scalar<<<1, 128>>>(lib, out, ofs > 0 ? 1 : 0);
    k_map<<<28, 256>>>(out + ofs);
}